// round 11
// baseline (speedup 1.0000x reference)
#include <cuda_runtime.h>
#include <cuda_bf16.h>
#include <math.h>
#include <stdint.h>

#define NB 64
#define NPIX 596
#define HEADS 4
#define DH 64
#define PER_B (HEADS*NPIX*DH)   // 152576
#define MROWS (NB*HEADS*NPIX)   // 152576
#define EROWS (NB*NPIX)         // 38144
#define KPAD 640

// ---- tf32 gemm common ----
#define KC 32                   // k-chunk in floats
#define NCH (KPAD/KC)           // 20
#define NCHL (128/KC)           // 4 (logits)
#define NCH1 (256/KC)           // 8 (lin1)
#define SKF 36                  // padded fp32 row stride (floats)
#define FBUF (128*SKF)          // one 128-row tile (floats)
#define VFBUF (64*SKF)
#define G_BUF (2*FBUF)                          // A + W tiles
#define GEMM_SMEM (2*G_BUF*4)                   // 73728 B
#define E_BUF (FBUF + VFBUF)
#define EGEMM_SMEM (2*E_BUF*4)                  // 55296 B

// ---------------- scratch ----------------
__device__ float g_conv1[NB*16*150*5];
__device__ float g_feats[NB*NPIX*34];
__device__ float g_K[NB*HEADS*NPIX*DH];
__device__ float g_Q[NB*HEADS*NPIX*DH];
__device__ float g_V[NB*HEADS*NPIX*DH];
__device__ float g_mu[3*NB], g_rv[3*NB];
__device__ float g_QKf[(size_t)MROWS*128];
__device__ float g_Wqkf[(size_t)KPAD*128];
__device__ float g_A[(size_t)MROWS*KPAD];
__device__ float g_Wf[(size_t)KPAD*KPAD];
__device__ float g_Vt[(size_t)NB*HEADS*DH*KPAD];
__device__ float g_W1t[64*256];
__device__ float g_S[(size_t)MROWS*NPIX];
__device__ float g_P[(size_t)MROWS*KPAD];
__device__ float g_E[(size_t)EROWS*256];
__device__ float g_F[EROWS*DH];
__device__ float g_mu2[NB], g_rv2[NB];
__device__ float g_M[NB*DH];

__device__ __forceinline__ float eluf(float x) {
    return x > 0.f ? x : (__expf(x) - 1.f);
}
__device__ __forceinline__ float tf32r(float x) {
    uint32_t u;
    asm("cvt.rna.tf32.f32 %0, %1;" : "=r"(u) : "f"(x));
    return __uint_as_float(u);
}

// ---- mma.sync tf32 ----
__device__ __forceinline__ void mma_tf32(float* c, const float* a, float b0, float b1) {
    asm volatile(
        "mma.sync.aligned.m16n8k8.row.col.f32.tf32.tf32.f32 "
        "{%0,%1,%2,%3}, {%4,%5,%6,%7}, {%8,%9}, {%0,%1,%2,%3};"
        : "+f"(c[0]), "+f"(c[1]), "+f"(c[2]), "+f"(c[3])
        : "r"(__float_as_uint(a[0])), "r"(__float_as_uint(a[1])),
          "r"(__float_as_uint(a[2])), "r"(__float_as_uint(a[3])),
          "r"(__float_as_uint(b0)), "r"(__float_as_uint(b1)));
}
// ---- cp.async ----
__device__ __forceinline__ void cp16(void* smem, const void* gmem) {
    uint32_t s = (uint32_t)__cvta_generic_to_shared(smem);
    asm volatile("cp.async.cg.shared.global [%0], [%1], 16;" :: "r"(s), "l"(gmem));
}
#define CP_COMMIT() asm volatile("cp.async.commit_group;" ::: "memory")
#define CP_WAIT1()  asm volatile("cp.async.wait_group 1;" ::: "memory")
#define CP_WAIT0()  asm volatile("cp.async.wait_group 0;" ::: "memory")

// ---------------- conv1 + relu ----------------
__global__ void conv1_kernel(const float* __restrict__ x,
                             const float* __restrict__ w,
                             const float* __restrict__ b) {
    int idx = blockIdx.x * blockDim.x + threadIdx.x;
    if (idx >= NB*16*150*5) return;
    int ow = idx % 5;
    int oh = (idx / 5) % 150;
    int co = (idx / (5*150)) % 16;
    int bb = idx / (5*150*16);
    float acc = b[co];
    #pragma unroll
    for (int ci = 0; ci < 4; ci++)
        #pragma unroll
        for (int kh = 0; kh < 2; kh++)
            #pragma unroll
            for (int kw = 0; kw < 2; kw++)
                acc += x[((bb*4+ci)*151 + oh+kh)*6 + ow+kw] *
                       w[((co*4+ci)*2 + kh)*2 + kw];
    g_conv1[idx] = fmaxf(acc, 0.f);
}

// ---------------- conv2 + relu + coords -> feats ----------------
__global__ void conv2_feats_kernel(const float* __restrict__ w,
                                   const float* __restrict__ b) {
    int idx = blockIdx.x * blockDim.x + threadIdx.x;
    if (idx >= NB*NPIX*34) return;
    int c = idx % 34;
    int p = (idx / 34) % NPIX;
    int bb = idx / (34*NPIX);
    int oh = p / 4, ow = p % 4;
    float val;
    if (c < 32) {
        float acc = b[c];
        #pragma unroll 4
        for (int ci = 0; ci < 16; ci++)
            #pragma unroll
            for (int kh = 0; kh < 2; kh++)
                #pragma unroll
                for (int kw = 0; kw < 2; kw++)
                    acc += g_conv1[((bb*16+ci)*150 + oh+kh)*5 + ow+kw] *
                           w[((c*16+ci)*2 + kh)*2 + kw];
        val = fmaxf(acc, 0.f);
    } else if (c == 32) {
        val = (float)ow / 4.f;
    } else {
        val = (float)oh / 149.f;
    }
    g_feats[idx] = val;
}

// ---------------- K/Q/V projections ----------------
__global__ void proj_kernel(const float* __restrict__ kw, const float* __restrict__ kb,
                            const float* __restrict__ qw, const float* __restrict__ qb,
                            const float* __restrict__ vw, const float* __restrict__ vb) {
    int t = blockIdx.y;
    const float* W = t==0 ? kw : t==1 ? qw : vw;
    const float* B = t==0 ? kb : t==1 ? qb : vb;
    float* O = t==0 ? g_K : t==1 ? g_Q : g_V;
    int idx = blockIdx.x * blockDim.x + threadIdx.x;
    if (idx >= NB*NPIX*256) return;
    int hd = idx & 255;
    int bp = idx >> 8;
    int p = bp % NPIX, bb = bp / NPIX;
    const float* f = g_feats + bp*34;
    float acc = B[hd];
    #pragma unroll
    for (int c = 0; c < 34; c++) acc += f[c] * W[c*256 + hd];
    int h = hd >> 6, d = hd & 63;
    O[((bb*HEADS + h)*NPIX + p)*DH + d] = acc;
}

// ---------------- LN stats (512 thr, float4) ----------------
__global__ __launch_bounds__(512) void ln_stats_kernel() {
    int bb = blockIdx.x, t = blockIdx.y;
    const float4* base = (const float4*)((t==0 ? g_K : t==1 ? g_Q : g_V) + bb*PER_B);
    const int n4 = PER_B/4;
    float s = 0.f, ss = 0.f;
    for (int i = threadIdx.x; i < n4; i += 512) {
        float4 v = base[i];
        s  += v.x + v.y + v.z + v.w;
        ss += v.x*v.x + v.y*v.y + v.z*v.z + v.w*v.w;
    }
    __shared__ double sh[512], sh2[512];
    sh[threadIdx.x] = (double)s; sh2[threadIdx.x] = (double)ss; __syncthreads();
    for (int o = 256; o; o >>= 1) {
        if (threadIdx.x < o) { sh[threadIdx.x] += sh[threadIdx.x+o]; sh2[threadIdx.x] += sh2[threadIdx.x+o]; }
        __syncthreads();
    }
    if (threadIdx.x == 0) {
        double m = sh[0] / (double)PER_B;
        double var = sh2[0] / (double)PER_B - m*m;
        g_mu[t*NB+bb] = (float)m;
        g_rv[t*NB+bb] = (float)(1.0 / sqrt(var + 1e-5));
    }
}

// ---------------- LN apply: Q,K -> tf32-rounded QK concat; V -> fp32 ----------------
__global__ void ln_apply_kernel(const float* __restrict__ kg, const float* __restrict__ kb,
                                const float* __restrict__ qg, const float* __restrict__ qb,
                                const float* __restrict__ vg, const float* __restrict__ vb) {
    int t = blockIdx.z;
    int bb = blockIdx.y;
    const float* base = (t==0 ? g_K : t==1 ? g_Q : g_V) + bb*PER_B;
    const float* g = t==0 ? kg : t==1 ? qg : vg;
    const float* be = t==0 ? kb : t==1 ? qb : vb;
    int off = (blockIdx.x*256 + threadIdx.x)*4;
    float mu = g_mu[t*NB+bb], rv = g_rv[t*NB+bb];
    float4 v  = *(const float4*)(base + off);
    float4 gg = *(const float4*)(g + off);
    float4 bv = *(const float4*)(be + off);
    float4 r;
    r.x = (v.x - mu)*rv*gg.x + bv.x;
    r.y = (v.y - mu)*rv*gg.y + bv.y;
    r.z = (v.z - mu)*rv*gg.z + bv.z;
    r.w = (v.w - mu)*rv*gg.w + bv.w;
    if (t == 2) {
        *(float4*)(g_V + bb*PER_B + off) = r;
    } else {
        int d = off & 63;
        int hp = off >> 6;
        size_t row = (size_t)bb*HEADS*NPIX + hp;
        int col = d + (t == 0 ? 64 : 0);
        float4 o;
        o.x = tf32r(r.x); o.y = tf32r(r.y); o.z = tf32r(r.z); o.w = tf32r(r.w);
        *(float4*)(g_QKf + row*128 + col) = o;
    }
}

// ---------------- V transpose (tf32-rounded): Vt[bh][d][p_pad] ----------------
__global__ void vtrans_kernel() {
    __shared__ float tile[32][65];
    int bhid = blockIdx.x;
    const float* Vb = g_V + (size_t)bhid*NPIX*DH;
    int t = threadIdx.x;
    for (int pt = 0; pt < 20; pt++) {
        int p0 = pt*32;
        for (int i = t; i < 32*64; i += 256) {
            int r = i >> 6, c = i & 63;
            tile[r][c] = (p0 + r < NPIX) ? Vb[(p0 + r)*DH + c] : 0.f;
        }
        __syncthreads();
        for (int i = t; i < 64*32; i += 256) {
            int d = i >> 5, pp = i & 31;
            g_Vt[((size_t)bhid*DH + d)*KPAD + p0 + pp] = tf32r(tile[pp][d]);
        }
        __syncthreads();
    }
}

// ---------------- merged weight prep: alin_w, [qlw;klw], lin1_w ----------------
__global__ void prep_all_kernel(const float* __restrict__ alw,
                                const float* __restrict__ qlw,
                                const float* __restrict__ klw,
                                const float* __restrict__ w1) {
    int idx = blockIdx.x*256 + threadIdx.x;
    if (idx < KPAD*KPAD) {
        int k = idx / KPAD, n = idx % KPAD;
        float v = (k < NPIX && n < NPIX) ? alw[k*NPIX + n] : 0.f;
        g_Wf[(size_t)n*KPAD + k] = tf32r(v);
        return;
    }
    idx -= KPAD*KPAD;
    if (idx < KPAD*128) {
        int n = idx >> 7, k = idx & 127;
        float v = 0.f;
        if (n < NPIX) v = (k < 64) ? qlw[k*NPIX + n] : klw[(k-64)*NPIX + n];
        g_Wqkf[(size_t)n*128 + k] = tf32r(v);
        return;
    }
    idx -= KPAD*128;
    if (idx < 64*256) {
        int d = idx >> 8, c = idx & 255;
        g_W1t[d*256 + c] = w1[c*64 + d];   // full fp32 (split happens in-kernel)
    }
}
#define PREP_TOT (KPAD*KPAD + KPAD*128 + 64*256)

// ---------------- pipelined cp.async tile loaders (fp32, 128 thr) ----------------
__device__ __forceinline__ void cp_ftile_t128(float* dst, const float* g,
                                              size_t row0, int kc, int tid, int gstride) {
    #pragma unroll
    for (int j = 0; j < 8; j++) {
        int idx = tid + j*128;               // 0..1023
        int r = idx >> 3, q = idx & 7;
        cp16(dst + r*SKF + q*4, g + (row0 + r)*(size_t)gstride + kc + q*4);
    }
}

// ---------------- tf32 GEMM inner step: 4 warps, warp tile 64x64 ----------------
__device__ __forceinline__ void tf32_step4(const float* sA, const float* sW, int ko,
                                           int wm, int wn, int g, int tig,
                                           float acc[4][8][4]) {
    float af[4][4];
    #pragma unroll
    for (int mi = 0; mi < 4; mi++) {
        const float* ar = sA + (wm*64 + mi*16 + g)*SKF + ko + tig;
        af[mi][0] = ar[0];
        af[mi][1] = ar[8*SKF];
        af[mi][2] = ar[4];
        af[mi][3] = ar[8*SKF + 4];
    }
    #pragma unroll
    for (int nsub = 0; nsub < 8; nsub++) {
        const float* br = sW + (wn*64 + nsub*8 + g)*SKF + ko + tig;
        float b0 = br[0], b1 = br[4];
        #pragma unroll
        for (int mi = 0; mi < 4; mi++)
            mma_tf32(acc[mi][nsub], af[mi], b0, b1);
    }
}

// ---------------- logits GEMM (tf32, 128 thr): A = elu(QK @ Wqk^T + bias) ----------------
__global__ __launch_bounds__(128, 2) void logits_gemm_kernel(
    const float* __restrict__ qlb, const float* __restrict__ klb) {
    extern __shared__ float fsm[];
    int tid = threadIdx.x;
    int lane = tid & 31;
    int wid = tid >> 5;
    int wm = wid & 1, wn = wid >> 1;
    int g = lane >> 2, tig = lane & 3;
    int n0 = blockIdx.x * 128;
    size_t m0 = (size_t)blockIdx.y * 128;

    float acc[4][8][4];
    #pragma unroll
    for (int mi = 0; mi < 4; mi++)
        #pragma unroll
        for (int ni = 0; ni < 8; ni++)
            #pragma unroll
            for (int k = 0; k < 4; k++) acc[mi][ni][k] = 0.f;

    {
        float* b = fsm;
        cp_ftile_t128(b,        g_QKf,  m0, 0, tid, 128);
        cp_ftile_t128(b + FBUF, g_Wqkf, n0, 0, tid, 128);
        CP_COMMIT();
    }
    for (int ch = 0; ch < NCHL; ch++) {
        if (ch + 1 < NCHL) {
            float* b = fsm + ((ch+1)&1)*G_BUF;
            int kc = (ch+1)*KC;
            cp_ftile_t128(b,        g_QKf,  m0, kc, tid, 128);
            cp_ftile_t128(b + FBUF, g_Wqkf, n0, kc, tid, 128);
            CP_COMMIT();
            CP_WAIT1();
        } else {
            CP_WAIT0();
        }
        __syncthreads();
        const float* sA = fsm + (ch&1)*G_BUF;
        const float* sW = sA + FBUF;
        #pragma unroll
        for (int ks = 0; ks < 4; ks++)
            tf32_step4(sA, sW, ks*8, wm, wn, g, tig, acc);
        __syncthreads();
    }

    #pragma unroll
    for (int mi = 0; mi < 4; mi++) {
        #pragma unroll
        for (int nsub = 0; nsub < 8; nsub++) {
            int n = n0 + wn*64 + nsub*8 + tig*2;
            float b0 = (n < NPIX)   ? qlb[n] + klb[n]     : 0.f;
            float b1 = (n+1 < NPIX) ? qlb[n+1] + klb[n+1] : 0.f;
            #pragma unroll
            for (int half = 0; half < 2; half++) {
                size_t m = m0 + wm*64 + mi*16 + g + half*8;
                float2 o;
                o.x = tf32r(eluf(acc[mi][nsub][2*half]   + b0));
                o.y = tf32r(eluf(acc[mi][nsub][2*half+1] + b1));
                *(float2*)(g_A + m*KPAD + n) = o;
            }
        }
    }
}

// ---------------- main GEMM (tf32, 128 thr): S = A @ W^T + alb ----------------
__global__ __launch_bounds__(128, 2) void gemm_kernel(const float* __restrict__ alb) {
    extern __shared__ float fsm[];
    int tid = threadIdx.x;
    int lane = tid & 31;
    int wid = tid >> 5;
    int wm = wid & 1, wn = wid >> 1;
    int g = lane >> 2, tig = lane & 3;
    int n0 = blockIdx.x * 128;
    size_t m0 = (size_t)blockIdx.y * 128;

    float acc[4][8][4];
    #pragma unroll
    for (int mi = 0; mi < 4; mi++)
        #pragma unroll
        for (int ni = 0; ni < 8; ni++)
            #pragma unroll
            for (int k = 0; k < 4; k++) acc[mi][ni][k] = 0.f;

    {
        float* b = fsm;
        cp_ftile_t128(b,        g_A,  m0, 0, tid, KPAD);
        cp_ftile_t128(b + FBUF, g_Wf, n0, 0, tid, KPAD);
        CP_COMMIT();
    }
    for (int ch = 0; ch < NCH; ch++) {
        if (ch + 1 < NCH) {
            float* b = fsm + ((ch+1)&1)*G_BUF;
            int kc = (ch+1)*KC;
            cp_ftile_t128(b,        g_A,  m0, kc, tid, KPAD);
            cp_ftile_t128(b + FBUF, g_Wf, n0, kc, tid, KPAD);
            CP_COMMIT();
            CP_WAIT1();
        } else {
            CP_WAIT0();
        }
        __syncthreads();
        const float* sA = fsm + (ch&1)*G_BUF;
        const float* sW = sA + FBUF;
        #pragma unroll
        for (int ks = 0; ks < 4; ks++)
            tf32_step4(sA, sW, ks*8, wm, wn, g, tig, acc);
        __syncthreads();
    }

    #pragma unroll
    for (int mi = 0; mi < 4; mi++) {
        #pragma unroll
        for (int nsub = 0; nsub < 8; nsub++) {
            int n = n0 + wn*64 + nsub*8 + tig*2;
            #pragma unroll
            for (int half = 0; half < 2; half++) {
                size_t m = m0 + wm*64 + mi*16 + g + half*8;
                if (n + 1 < NPIX) {
                    float2 o;
                    o.x = acc[mi][nsub][2*half]   + alb[n];
                    o.y = acc[mi][nsub][2*half+1] + alb[n+1];
                    *(float2*)(g_S + m*NPIX + n) = o;
                } else if (n < NPIX) {
                    g_S[m*NPIX + n] = acc[mi][nsub][2*half] + alb[n];
                }
            }
        }
    }
}

// ---------------- softmax (float4): g_S -> g_P (tf32-rounded, zero-padded) ----------------
__global__ __launch_bounds__(256) void softmax_kernel() {
    size_t row = (size_t)blockIdx.x*8 + (threadIdx.x >> 5);
    int lane = threadIdx.x & 31;
    const float4* S4 = (const float4*)(g_S + row*NPIX);   // 149 float4s
    float* P = g_P + row*KPAD;
    float4 v[5];
    float m = -1e30f;
    #pragma unroll
    for (int i = 0; i < 5; i++) {
        int j = lane + 32*i;
        if (j < 149) {
            v[i] = S4[j];
            m = fmaxf(m, fmaxf(fmaxf(v[i].x, v[i].y), fmaxf(v[i].z, v[i].w)));
        } else {
            v[i].x = v[i].y = v[i].z = v[i].w = -1e30f;
        }
    }
    #pragma unroll
    for (int o = 16; o; o >>= 1) m = fmaxf(m, __shfl_xor_sync(0xffffffffu, m, o));
    float s = 0.f;
    #pragma unroll
    for (int i = 0; i < 5; i++) {
        v[i].x = __expf(v[i].x - m); v[i].y = __expf(v[i].y - m);
        v[i].z = __expf(v[i].z - m); v[i].w = __expf(v[i].w - m);
        if (lane + 32*i < 149) s += v[i].x + v[i].y + v[i].z + v[i].w;
    }
    #pragma unroll
    for (int o = 16; o; o >>= 1) s += __shfl_xor_sync(0xffffffffu, s, o);
    float inv = 1.f / s;
    #pragma unroll
    for (int i = 0; i < 5; i++) {
        int j = lane + 32*i;
        if (j < 149) {
            float4 o;
            o.x = tf32r(v[i].x*inv); o.y = tf32r(v[i].y*inv);
            o.z = tf32r(v[i].z*inv); o.w = tf32r(v[i].w*inv);
            *(float4*)(P + 4*j) = o;
        }
    }
    // zero pad 596..639 (11 float4s)
    if (lane < 11) {
        float4 z; z.x = z.y = z.z = z.w = 0.f;
        *(float4*)(P + 596 + 4*lane) = z;
    }
}

// ---------------- E GEMM (tf32): E = P @ Vt^T per bh (fp32 out, no rounding) ----------------
__global__ __launch_bounds__(256, 2) void e_gemm_kernel() {
    extern __shared__ float fsm[];
    int tid = threadIdx.x;
    int lane = tid & 31;
    int wid = tid >> 5;
    int g = lane >> 2, tig = lane & 3;
    int mt = blockIdx.x;
    int bhid = blockIdx.y;
    int p00 = mt * 128;
    int bb = bhid >> 2, h = bhid & 3;

    float acc[8][4];
    #pragma unroll
    for (int ni = 0; ni < 8; ni++)
        #pragma unroll
        for (int k = 0; k < 4; k++) acc[ni][k] = 0.f;

    auto loadT = [&](float* b, int kc) {
        #pragma unroll
        for (int j = 0; j < 4; j++) {
            int idx = tid + j*256;
            int r = idx >> 3, q = idx & 7;
            int p = p00 + r; if (p > NPIX-1) p = NPIX-1;
            cp16(b + r*SKF + q*4, g_P + ((size_t)bhid*NPIX + p)*KPAD + kc + q*4);
        }
        #pragma unroll
        for (int j = 0; j < 2; j++) {
            int idx = tid + j*256;
            int r = idx >> 3, q = idx & 7;
            cp16(b + FBUF + r*SKF + q*4, g_Vt + ((size_t)bhid*DH + r)*KPAD + kc + q*4);
        }
    };

    loadT(fsm, 0);
    CP_COMMIT();
    for (int ch = 0; ch < NCH; ch++) {
        if (ch + 1 < NCH) {
            loadT(fsm + ((ch+1)&1)*E_BUF, (ch+1)*KC);
            CP_COMMIT();
            CP_WAIT1();
        } else {
            CP_WAIT0();
        }
        __syncthreads();
        const float* sP = fsm + (ch&1)*E_BUF;
        const float* sV = sP + FBUF;
        #pragma unroll
        for (int ks = 0; ks < 4; ks++) {
            int ko = ks*8;
            float af[4];
            const float* ar = sP + (wid*16 + g)*SKF + ko + tig;
            af[0] = ar[0];
            af[1] = ar[8*SKF];
            af[2] = ar[4];
            af[3] = ar[8*SKF + 4];
            #pragma unroll
            for (int nsub = 0; nsub < 8; nsub++) {
                const float* br = sV + (nsub*8 + g)*SKF + ko + tig;
                mma_tf32(acc[nsub], af, br[0], br[4]);
            }
        }
        __syncthreads();
    }

    #pragma unroll
    for (int nsub = 0; nsub < 8; nsub++) {
        int d = nsub*8 + tig*2;
        #pragma unroll
        for (int half = 0; half < 2; half++) {
            int p = p00 + wid*16 + g + half*8;
            if (p < NPIX) {
                float2 o; o.x = acc[nsub][2*half]; o.y = acc[nsub][2*half+1];
                *(float2*)(g_E + ((size_t)bb*NPIX + p)*256 + h*DH + d) = o;
            }
        }
    }
}

// ---------------- lin1 GEMM (tf32, 3-term split): F = relu(E @ W1t^T + b) ----------------
__global__ __launch_bounds__(256, 2) void lin1_gemm_kernel(const float* __restrict__ b1) {
    extern __shared__ float fsm[];
    int tid = threadIdx.x;
    int lane = tid & 31;
    int wid = tid >> 5;
    int g = lane >> 2, tig = lane & 3;
    size_t m0 = (size_t)blockIdx.x * 128;

    float acc[8][4];
    #pragma unroll
    for (int ni = 0; ni < 8; ni++)
        #pragma unroll
        for (int k = 0; k < 4; k++) acc[ni][k] = 0.f;

    auto loadT = [&](float* b, int kc) {
        #pragma unroll
        for (int j = 0; j < 4; j++) {
            int idx = tid + j*256;
            int r = idx >> 3, q = idx & 7;
            cp16(b + r*SKF + q*4, g_E + (m0 + r)*256 + kc + q*4);
        }
        #pragma unroll
        for (int j = 0; j < 2; j++) {
            int idx = tid + j*256;
            int r = idx >> 3, q = idx & 7;
            cp16(b + FBUF + r*SKF + q*4, g_W1t + r*256 + kc + q*4);
        }
    };

    loadT(fsm, 0);
    CP_COMMIT();
    for (int ch = 0; ch < NCH1; ch++) {
        if (ch + 1 < NCH1) {
            loadT(fsm + ((ch+1)&1)*E_BUF, (ch+1)*KC);
            CP_COMMIT();
            CP_WAIT1();
        } else {
            CP_WAIT0();
        }
        __syncthreads();
        const float* sE = fsm + (ch&1)*E_BUF;
        const float* sW = sE + FBUF;
        #pragma unroll
        for (int ks = 0; ks < 4; ks++) {
            int ko = ks*8;
            float raw[4], eh[4], el[4];
            const float* ar = sE + (wid*16 + g)*SKF + ko + tig;
            raw[0] = ar[0];
            raw[1] = ar[8*SKF];
            raw[2] = ar[4];
            raw[3] = ar[8*SKF + 4];
            #pragma unroll
            for (int q = 0; q < 4; q++) {
                eh[q] = tf32r(raw[q]);
                el[q] = tf32r(raw[q] - eh[q]);
            }
            #pragma unroll
            for (int nsub = 0; nsub < 8; nsub++) {
                const float* br = sW + (nsub*8 + g)*SKF + ko + tig;
                float w0 = br[0], w1 = br[4];
                float wh0 = tf32r(w0), wh1 = tf32r(w1);
                float wl0 = tf32r(w0 - wh0), wl1 = tf32r(w1 - wh1);
                mma_tf32(acc[nsub], eh, wh0, wh1);
                mma_tf32(acc[nsub], eh, wl0, wl1);
                mma_tf32(acc[nsub], el, wh0, wh1);
            }
        }
        __syncthreads();
    }

    #pragma unroll
    for (int nsub = 0; nsub < 8; nsub++) {
        int d = nsub*8 + tig*2;
        float bb0 = b1[d], bb1 = b1[d+1];
        #pragma unroll
        for (int half = 0; half < 2; half++) {
            size_t m = m0 + wid*16 + g + half*8;
            float2 o;
            o.x = fmaxf(acc[nsub][2*half]   + bb0, 0.f);
            o.y = fmaxf(acc[nsub][2*half+1] + bb1, 0.f);
            *(float2*)(g_F + m*DH + d) = o;
        }
    }
}

// ---------------- LN2 stats ----------------
__global__ void ln2_stats_kernel() {
    int bb = blockIdx.x;
    const float4* base = (const float4*)(g_F + bb*NPIX*DH);
    const int n4 = NPIX*DH/4;
    float s = 0.f, ss = 0.f;
    for (int i = threadIdx.x; i < n4; i += blockDim.x) {
        float4 v = base[i];
        s  += v.x + v.y + v.z + v.w;
        ss += v.x*v.x + v.y*v.y + v.z*v.z + v.w*v.w;
    }
    __shared__ double sh[256], sh2[256];
    sh[threadIdx.x] = (double)s; sh2[threadIdx.x] = (double)ss; __syncthreads();
    for (int o = 128; o; o >>= 1) {
        if (threadIdx.x < o) { sh[threadIdx.x] += sh[threadIdx.x+o]; sh2[threadIdx.x] += sh2[threadIdx.x+o]; }
        __syncthreads();
    }
    if (threadIdx.x == 0) {
        const int n = NPIX*DH;
        double m = sh[0] / (double)n;
        double var = sh2[0] / (double)n - m*m;
        g_mu2[bb] = (float)m;
        g_rv2[bb] = (float)(1.0 / sqrt(var + 1e-5));
    }
}

// ---------------- LN2 apply + max ----------------
__global__ void ln2max_kernel() {
    int bb = blockIdx.x;
    int d = threadIdx.x & 63, pc = threadIdx.x >> 6;
    float mu = g_mu2[bb], rv = g_rv2[bb];
    float m = -1e30f;
    for (int p = pc; p < NPIX; p += 4) {
        float v = (g_F[(bb*NPIX + p)*DH + d] - mu) * rv;
        m = fmaxf(m, v);
    }
    __shared__ float sh[256];
    sh[threadIdx.x] = m; __syncthreads();
    if (pc == 0) {
        m = fmaxf(fmaxf(sh[d], sh[64+d]), fmaxf(sh[128+d], sh[192+d]));
        g_M[bb*DH + d] = m;
    }
}

// ---------------- final lin2 + elu ----------------
__global__ void final_kernel(const float* __restrict__ w, const float* __restrict__ b,
                             float* __restrict__ out) {
    int idx = blockIdx.x * blockDim.x + threadIdx.x;
    if (idx >= NB*10) return;
    int bb = idx / 10, j = idx % 10;
    float acc = b[j];
    #pragma unroll
    for (int d = 0; d < DH; d++) acc += g_M[bb*DH + d] * w[d*10 + j];
    out[idx] = eluf(acc);
}

extern "C" void kernel_launch(void* const* d_in, const int* in_sizes, int n_in,
                              void* d_out, int out_size) {
    const float* x       = (const float*)d_in[0];
    const float* conv1_w = (const float*)d_in[1];
    const float* conv1_b = (const float*)d_in[2];
    const float* conv2_w = (const float*)d_in[3];
    const float* conv2_b = (const float*)d_in[4];
    const float* kp_w    = (const float*)d_in[5];
    const float* kp_b    = (const float*)d_in[6];
    const float* qp_w    = (const float*)d_in[7];
    const float* qp_b    = (const float*)d_in[8];
    const float* vp_w    = (const float*)d_in[9];
    const float* vp_b    = (const float*)d_in[10];
    const float* klin_w  = (const float*)d_in[11];
    const float* klin_b  = (const float*)d_in[12];
    const float* qlin_w  = (const float*)d_in[13];
    const float* qlin_b  = (const float*)d_in[14];
    const float* alin_w  = (const float*)d_in[15];
    const float* alin_b  = (const float*)d_in[16];
    const float* knorm_g = (const float*)d_in[17];
    const float* knorm_b = (const float*)d_in[18];
    const float* qnorm_g = (const float*)d_in[19];
    const float* qnorm_b = (const float*)d_in[20];
    const float* vnorm_g = (const float*)d_in[21];
    const float* vnorm_b = (const float*)d_in[22];
    const float* lin1_w  = (const float*)d_in[23];
    const float* lin1_b  = (const float*)d_in[24];
    const float* lin2_w  = (const float*)d_in[25];
    const float* lin2_b  = (const float*)d_in[26];
    float* out = (float*)d_out;

    cudaFuncSetAttribute(logits_gemm_kernel, cudaFuncAttributeMaxDynamicSharedMemorySize, GEMM_SMEM);
    cudaFuncSetAttribute(gemm_kernel,        cudaFuncAttributeMaxDynamicSharedMemorySize, GEMM_SMEM);
    cudaFuncSetAttribute(e_gemm_kernel,      cudaFuncAttributeMaxDynamicSharedMemorySize, EGEMM_SMEM);
    cudaFuncSetAttribute(lin1_gemm_kernel,   cudaFuncAttributeMaxDynamicSharedMemorySize, EGEMM_SMEM);

    conv1_kernel<<<(NB*16*150*5 + 255)/256, 256>>>(x, conv1_w, conv1_b);
    conv2_feats_kernel<<<(NB*NPIX*34 + 255)/256, 256>>>(conv2_w, conv2_b);
    {
        dim3 g((NB*NPIX*256 + 255)/256, 3);
        proj_kernel<<<g, 256>>>(kp_w, kp_b, qp_w, qp_b, vp_w, vp_b);
    }
    {
        dim3 g(NB, 3);
        ln_stats_kernel<<<g, 512>>>();
    }
    {
        dim3 g(PER_B/1024, NB, 3);
        ln_apply_kernel<<<g, 256>>>(knorm_g, knorm_b, qnorm_g, qnorm_b, vnorm_g, vnorm_b);
    }
    prep_all_kernel<<<(PREP_TOT + 255)/256, 256>>>(alin_w, qlin_w, klin_w, lin1_w);
    {
        dim3 g(KPAD/128, MROWS/128);               // (5, 1192)
        logits_gemm_kernel<<<g, 128, GEMM_SMEM>>>(qlin_b, klin_b);
    }
    {
        dim3 g(KPAD/128, MROWS/128);               // (5, 1192)
        gemm_kernel<<<g, 128, GEMM_SMEM>>>(alin_b);
    }
    vtrans_kernel<<<NB*HEADS, 256>>>();
    softmax_kernel<<<MROWS/8, 256>>>();
    {
        dim3 g(5, NB*HEADS);                       // (5, 256)
        e_gemm_kernel<<<g, 256, EGEMM_SMEM>>>();
    }
    lin1_gemm_kernel<<<EROWS/128, 256, EGEMM_SMEM>>>(lin1_b);
    ln2_stats_kernel<<<NB, 256>>>();
    ln2max_kernel<<<NB, 256>>>();
    final_kernel<<<3, 256>>>(lin2_w, lin2_b, out);
}

// round 12
// speedup vs baseline: 1.0954x; 1.0954x over previous
#include <cuda_runtime.h>
#include <cuda_bf16.h>
#include <math.h>
#include <stdint.h>

#define NB 64
#define NPIX 596
#define HEADS 4
#define DH 64
#define PER_B (HEADS*NPIX*DH)   // 152576
#define MROWS (NB*HEADS*NPIX)   // 152576
#define EROWS (NB*NPIX)         // 38144
#define KPAD 640

// ---- tf32 gemm common ----
#define KC 32                   // k-chunk in floats
#define NCH (KPAD/KC)           // 20
#define NCHL (128/KC)           // 4 (logits)
#define NCH1 (256/KC)           // 8 (lin1)
#define NCHP (64/KC)            // 2 (proj)
#define SKF 36                  // padded fp32 row stride (floats)
#define FBUF (128*SKF)          // one 128-row tile (floats)
#define VFBUF (64*SKF)
#define G_BUF (2*FBUF)                          // A + W tiles
#define GEMM_SMEM (2*G_BUF*4)                   // 73728 B
#define E_BUF (FBUF + VFBUF)
#define EGEMM_SMEM (2*E_BUF*4)                  // 55296 B

// ---------------- scratch ----------------
__device__ float g_conv1[NB*16*150*5];
__device__ float g_feats[(size_t)EROWS*64];     // [b*p][64] zero-padded feats
__device__ float g_K[NB*HEADS*NPIX*DH];
__device__ float g_Q[NB*HEADS*NPIX*DH];
__device__ float g_V[NB*HEADS*NPIX*DH];
__device__ float g_Wkqv[768*64];                // [k|q|v out-channel][feat]
__device__ float g_mu[3*NB], g_rv[3*NB];
__device__ float g_QKf[(size_t)MROWS*128];
__device__ float g_Wqkf[(size_t)KPAD*128];
__device__ float g_A[(size_t)MROWS*KPAD];
__device__ float g_Wf[(size_t)KPAD*KPAD];
__device__ float g_Vt[(size_t)NB*HEADS*DH*KPAD];
__device__ float g_W1t[64*256];
__device__ float g_S[(size_t)MROWS*NPIX];
__device__ float g_P[(size_t)MROWS*KPAD];
__device__ float g_E[(size_t)EROWS*256];
__device__ float g_F[EROWS*DH];
__device__ float g_mu2[NB], g_rv2[NB];
__device__ float g_M[NB*DH];

__device__ __forceinline__ float eluf(float x) {
    return x > 0.f ? x : (__expf(x) - 1.f);
}
__device__ __forceinline__ float tf32r(float x) {
    uint32_t u;
    asm("cvt.rna.tf32.f32 %0, %1;" : "=r"(u) : "f"(x));
    return __uint_as_float(u);
}

// ---- mma.sync tf32 ----
__device__ __forceinline__ void mma_tf32(float* c, const float* a, float b0, float b1) {
    asm volatile(
        "mma.sync.aligned.m16n8k8.row.col.f32.tf32.tf32.f32 "
        "{%0,%1,%2,%3}, {%4,%5,%6,%7}, {%8,%9}, {%0,%1,%2,%3};"
        : "+f"(c[0]), "+f"(c[1]), "+f"(c[2]), "+f"(c[3])
        : "r"(__float_as_uint(a[0])), "r"(__float_as_uint(a[1])),
          "r"(__float_as_uint(a[2])), "r"(__float_as_uint(a[3])),
          "r"(__float_as_uint(b0)), "r"(__float_as_uint(b1)));
}
// ---- cp.async ----
__device__ __forceinline__ void cp16(void* smem, const void* gmem) {
    uint32_t s = (uint32_t)__cvta_generic_to_shared(smem);
    asm volatile("cp.async.cg.shared.global [%0], [%1], 16;" :: "r"(s), "l"(gmem));
}
#define CP_COMMIT() asm volatile("cp.async.commit_group;" ::: "memory")
#define CP_WAIT1()  asm volatile("cp.async.wait_group 1;" ::: "memory")
#define CP_WAIT0()  asm volatile("cp.async.wait_group 0;" ::: "memory")

// ---------------- conv1 + relu ----------------
__global__ void conv1_kernel(const float* __restrict__ x,
                             const float* __restrict__ w,
                             const float* __restrict__ b) {
    int idx = blockIdx.x * blockDim.x + threadIdx.x;
    if (idx >= NB*16*150*5) return;
    int ow = idx % 5;
    int oh = (idx / 5) % 150;
    int co = (idx / (5*150)) % 16;
    int bb = idx / (5*150*16);
    float acc = b[co];
    #pragma unroll
    for (int ci = 0; ci < 4; ci++)
        #pragma unroll
        for (int kh = 0; kh < 2; kh++)
            #pragma unroll
            for (int kw = 0; kw < 2; kw++)
                acc += x[((bb*4+ci)*151 + oh+kh)*6 + ow+kw] *
                       w[((co*4+ci)*2 + kh)*2 + kw];
    g_conv1[idx] = fmaxf(acc, 0.f);
}

// ---------------- conv2 + relu + coords -> feats [b*p][64] zero-padded ----------------
__global__ void conv2_feats_kernel(const float* __restrict__ w,
                                   const float* __restrict__ b) {
    int idx = blockIdx.x * blockDim.x + threadIdx.x;
    if (idx >= EROWS*64) return;
    int c = idx & 63;
    int bp = idx >> 6;
    int p = bp % NPIX;
    int bb = bp / NPIX;
    int oh = p / 4, ow = p % 4;
    float val;
    if (c < 32) {
        float acc = b[c];
        #pragma unroll 4
        for (int ci = 0; ci < 16; ci++)
            #pragma unroll
            for (int kh = 0; kh < 2; kh++)
                #pragma unroll
                for (int kw = 0; kw < 2; kw++)
                    acc += g_conv1[((bb*16+ci)*150 + oh+kh)*5 + ow+kw] *
                           w[((c*16+ci)*2 + kh)*2 + kw];
        val = fmaxf(acc, 0.f);
    } else if (c == 32) {
        val = (float)ow / 4.f;
    } else if (c == 33) {
        val = (float)oh / 149.f;
    } else {
        val = 0.f;
    }
    g_feats[idx] = val;
}

// ---------------- proj GEMM (tf32 3-term): [K|Q|V] = feats @ Wkqv^T + bias ----------------
__global__ __launch_bounds__(256, 2) void proj_gemm_kernel(
    const float* __restrict__ kb, const float* __restrict__ qb,
    const float* __restrict__ vb) {
    extern __shared__ float fsm[];
    int tid = threadIdx.x;
    int lane = tid & 31;
    int wid = tid >> 5;
    int g = lane >> 2, tig = lane & 3;
    size_t m0 = (size_t)blockIdx.x * 128;
    int n0 = blockIdx.y * 64;

    float acc[8][4];
    #pragma unroll
    for (int ni = 0; ni < 8; ni++)
        #pragma unroll
        for (int k = 0; k < 4; k++) acc[ni][k] = 0.f;

    auto loadT = [&](float* b, int kc) {
        #pragma unroll
        for (int j = 0; j < 4; j++) {
            int idx = tid + j*256;
            int r = idx >> 3, q = idx & 7;
            cp16(b + r*SKF + q*4, g_feats + (m0 + r)*64 + kc + q*4);
        }
        #pragma unroll
        for (int j = 0; j < 2; j++) {
            int idx = tid + j*256;
            int r = idx >> 3, q = idx & 7;
            cp16(b + FBUF + r*SKF + q*4, g_Wkqv + (n0 + r)*64 + kc + q*4);
        }
    };

    loadT(fsm, 0);
    CP_COMMIT();
    for (int ch = 0; ch < NCHP; ch++) {
        if (ch + 1 < NCHP) {
            loadT(fsm + ((ch+1)&1)*E_BUF, (ch+1)*KC);
            CP_COMMIT();
            CP_WAIT1();
        } else {
            CP_WAIT0();
        }
        __syncthreads();
        const float* sE = fsm + (ch&1)*E_BUF;
        const float* sW = sE + FBUF;
        #pragma unroll
        for (int ks = 0; ks < 4; ks++) {
            int ko = ks*8;
            float raw[4], eh[4], el[4];
            const float* ar = sE + (wid*16 + g)*SKF + ko + tig;
            raw[0] = ar[0];
            raw[1] = ar[8*SKF];
            raw[2] = ar[4];
            raw[3] = ar[8*SKF + 4];
            #pragma unroll
            for (int q = 0; q < 4; q++) {
                eh[q] = tf32r(raw[q]);
                el[q] = tf32r(raw[q] - eh[q]);
            }
            #pragma unroll
            for (int nsub = 0; nsub < 8; nsub++) {
                const float* br = sW + (nsub*8 + g)*SKF + ko + tig;
                float w0 = br[0], w1 = br[4];
                float wh0 = tf32r(w0), wh1 = tf32r(w1);
                float wl0 = tf32r(w0 - wh0), wl1 = tf32r(w1 - wh1);
                mma_tf32(acc[nsub], eh, wh0, wh1);
                mma_tf32(acc[nsub], eh, wl0, wl1);
                mma_tf32(acc[nsub], el, wh0, wh1);
            }
        }
        __syncthreads();
    }

    // epilogue: scatter into g_K/g_Q/g_V with bias
    int mloc[2], bbv[2], pv[2];
    #pragma unroll
    for (int half = 0; half < 2; half++) {
        mloc[half] = (int)(m0 + wid*16 + g + half*8);
        bbv[half] = mloc[half] / NPIX;
        pv[half]  = mloc[half] % NPIX;
    }
    #pragma unroll
    for (int nsub = 0; nsub < 8; nsub++) {
        int n = n0 + nsub*8 + tig*2;       // 0..767
        int t = n >> 8;                    // 0=K, 1=Q, 2=V
        int hd = n & 255;
        int h = hd >> 6, d = hd & 63;
        const float* B = t == 0 ? kb : t == 1 ? qb : vb;
        float* O = t == 0 ? g_K : t == 1 ? g_Q : g_V;
        float b0 = B[hd], b1 = B[hd+1];
        #pragma unroll
        for (int half = 0; half < 2; half++) {
            float2 o;
            o.x = acc[nsub][2*half]   + b0;
            o.y = acc[nsub][2*half+1] + b1;
            *(float2*)(O + ((size_t)(bbv[half]*HEADS + h)*NPIX + pv[half])*DH + d) = o;
        }
    }
}

// ---------------- LN stats (512 thr, float4) ----------------
__global__ __launch_bounds__(512) void ln_stats_kernel() {
    int bb = blockIdx.x, t = blockIdx.y;
    const float4* base = (const float4*)((t==0 ? g_K : t==1 ? g_Q : g_V) + bb*PER_B);
    const int n4 = PER_B/4;
    float s = 0.f, ss = 0.f;
    for (int i = threadIdx.x; i < n4; i += 512) {
        float4 v = base[i];
        s  += v.x + v.y + v.z + v.w;
        ss += v.x*v.x + v.y*v.y + v.z*v.z + v.w*v.w;
    }
    __shared__ double sh[512], sh2[512];
    sh[threadIdx.x] = (double)s; sh2[threadIdx.x] = (double)ss; __syncthreads();
    for (int o = 256; o; o >>= 1) {
        if (threadIdx.x < o) { sh[threadIdx.x] += sh[threadIdx.x+o]; sh2[threadIdx.x] += sh2[threadIdx.x+o]; }
        __syncthreads();
    }
    if (threadIdx.x == 0) {
        double m = sh[0] / (double)PER_B;
        double var = sh2[0] / (double)PER_B - m*m;
        g_mu[t*NB+bb] = (float)m;
        g_rv[t*NB+bb] = (float)(1.0 / sqrt(var + 1e-5));
    }
}

// ---------------- LN apply: Q,K -> tf32-rounded QK concat; V -> fp32 ----------------
__global__ void ln_apply_kernel(const float* __restrict__ kg, const float* __restrict__ kb,
                                const float* __restrict__ qg, const float* __restrict__ qb,
                                const float* __restrict__ vg, const float* __restrict__ vb) {
    int t = blockIdx.z;
    int bb = blockIdx.y;
    const float* base = (t==0 ? g_K : t==1 ? g_Q : g_V) + bb*PER_B;
    const float* g = t==0 ? kg : t==1 ? qg : vg;
    const float* be = t==0 ? kb : t==1 ? qb : vb;
    int off = (blockIdx.x*256 + threadIdx.x)*4;
    float mu = g_mu[t*NB+bb], rv = g_rv[t*NB+bb];
    float4 v  = *(const float4*)(base + off);
    float4 gg = *(const float4*)(g + off);
    float4 bv = *(const float4*)(be + off);
    float4 r;
    r.x = (v.x - mu)*rv*gg.x + bv.x;
    r.y = (v.y - mu)*rv*gg.y + bv.y;
    r.z = (v.z - mu)*rv*gg.z + bv.z;
    r.w = (v.w - mu)*rv*gg.w + bv.w;
    if (t == 2) {
        *(float4*)(g_V + bb*PER_B + off) = r;
    } else {
        int d = off & 63;
        int hp = off >> 6;
        size_t row = (size_t)bb*HEADS*NPIX + hp;
        int col = d + (t == 0 ? 64 : 0);
        float4 o;
        o.x = tf32r(r.x); o.y = tf32r(r.y); o.z = tf32r(r.z); o.w = tf32r(r.w);
        *(float4*)(g_QKf + row*128 + col) = o;
    }
}

// ---------------- V transpose (tf32-rounded): Vt[bh][d][p_pad] ----------------
__global__ void vtrans_kernel() {
    __shared__ float tile[32][65];
    int bhid = blockIdx.x;
    const float* Vb = g_V + (size_t)bhid*NPIX*DH;
    int t = threadIdx.x;
    for (int pt = 0; pt < 20; pt++) {
        int p0 = pt*32;
        for (int i = t; i < 32*64; i += 256) {
            int r = i >> 6, c = i & 63;
            tile[r][c] = (p0 + r < NPIX) ? Vb[(p0 + r)*DH + c] : 0.f;
        }
        __syncthreads();
        for (int i = t; i < 64*32; i += 256) {
            int d = i >> 5, pp = i & 31;
            g_Vt[((size_t)bhid*DH + d)*KPAD + p0 + pp] = tf32r(tile[pp][d]);
        }
        __syncthreads();
    }
}

// ---------------- merged weight prep: alin_w, [qlw;klw], lin1_w, Wkqv ----------------
__global__ void prep_all_kernel(const float* __restrict__ alw,
                                const float* __restrict__ qlw,
                                const float* __restrict__ klw,
                                const float* __restrict__ w1,
                                const float* __restrict__ kpw,
                                const float* __restrict__ qpw,
                                const float* __restrict__ vpw) {
    int idx = blockIdx.x*256 + threadIdx.x;
    if (idx < KPAD*KPAD) {
        int k = idx / KPAD, n = idx % KPAD;
        float v = (k < NPIX && n < NPIX) ? alw[k*NPIX + n] : 0.f;
        g_Wf[(size_t)n*KPAD + k] = tf32r(v);
        return;
    }
    idx -= KPAD*KPAD;
    if (idx < KPAD*128) {
        int n = idx >> 7, k = idx & 127;
        float v = 0.f;
        if (n < NPIX) v = (k < 64) ? qlw[k*NPIX + n] : klw[(k-64)*NPIX + n];
        g_Wqkf[(size_t)n*128 + k] = tf32r(v);
        return;
    }
    idx -= KPAD*128;
    if (idx < 64*256) {
        int d = idx >> 8, c = idx & 255;
        g_W1t[d*256 + c] = w1[c*64 + d];   // full fp32 (split in-kernel)
        return;
    }
    idx -= 64*256;
    if (idx < 768*64) {
        int n = idx >> 6, c = idx & 63;    // n: 0..767 = [k|q|v]*256+hd
        int t = n >> 8, hd = n & 255;
        const float* W = t == 0 ? kpw : t == 1 ? qpw : vpw;
        g_Wkqv[n*64 + c] = (c < 34) ? W[c*256 + hd] : 0.f;  // full fp32 (split in-kernel)
    }
}
#define PREP_TOT (KPAD*KPAD + KPAD*128 + 64*256 + 768*64)

// ---------------- pipelined cp.async tile loaders (fp32, 128 thr) ----------------
__device__ __forceinline__ void cp_ftile_t128(float* dst, const float* g,
                                              size_t row0, int kc, int tid, int gstride) {
    #pragma unroll
    for (int j = 0; j < 8; j++) {
        int idx = tid + j*128;               // 0..1023
        int r = idx >> 3, q = idx & 7;
        cp16(dst + r*SKF + q*4, g + (row0 + r)*(size_t)gstride + kc + q*4);
    }
}

// ---------------- tf32 GEMM inner step: 4 warps, warp tile 64x64 ----------------
__device__ __forceinline__ void tf32_step4(const float* sA, const float* sW, int ko,
                                           int wm, int wn, int g, int tig,
                                           float acc[4][8][4]) {
    float af[4][4];
    #pragma unroll
    for (int mi = 0; mi < 4; mi++) {
        const float* ar = sA + (wm*64 + mi*16 + g)*SKF + ko + tig;
        af[mi][0] = ar[0];
        af[mi][1] = ar[8*SKF];
        af[mi][2] = ar[4];
        af[mi][3] = ar[8*SKF + 4];
    }
    #pragma unroll
    for (int nsub = 0; nsub < 8; nsub++) {
        const float* br = sW + (wn*64 + nsub*8 + g)*SKF + ko + tig;
        float b0 = br[0], b1 = br[4];
        #pragma unroll
        for (int mi = 0; mi < 4; mi++)
            mma_tf32(acc[mi][nsub], af[mi], b0, b1);
    }
}

// ---------------- logits GEMM (tf32, 128 thr): A = elu(QK @ Wqk^T + bias) ----------------
__global__ __launch_bounds__(128, 2) void logits_gemm_kernel(
    const float* __restrict__ qlb, const float* __restrict__ klb) {
    extern __shared__ float fsm[];
    int tid = threadIdx.x;
    int lane = tid & 31;
    int wid = tid >> 5;
    int wm = wid & 1, wn = wid >> 1;
    int g = lane >> 2, tig = lane & 3;
    int n0 = blockIdx.x * 128;
    size_t m0 = (size_t)blockIdx.y * 128;

    float acc[4][8][4];
    #pragma unroll
    for (int mi = 0; mi < 4; mi++)
        #pragma unroll
        for (int ni = 0; ni < 8; ni++)
            #pragma unroll
            for (int k = 0; k < 4; k++) acc[mi][ni][k] = 0.f;

    {
        float* b = fsm;
        cp_ftile_t128(b,        g_QKf,  m0, 0, tid, 128);
        cp_ftile_t128(b + FBUF, g_Wqkf, n0, 0, tid, 128);
        CP_COMMIT();
    }
    for (int ch = 0; ch < NCHL; ch++) {
        if (ch + 1 < NCHL) {
            float* b = fsm + ((ch+1)&1)*G_BUF;
            int kc = (ch+1)*KC;
            cp_ftile_t128(b,        g_QKf,  m0, kc, tid, 128);
            cp_ftile_t128(b + FBUF, g_Wqkf, n0, kc, tid, 128);
            CP_COMMIT();
            CP_WAIT1();
        } else {
            CP_WAIT0();
        }
        __syncthreads();
        const float* sA = fsm + (ch&1)*G_BUF;
        const float* sW = sA + FBUF;
        #pragma unroll
        for (int ks = 0; ks < 4; ks++)
            tf32_step4(sA, sW, ks*8, wm, wn, g, tig, acc);
        __syncthreads();
    }

    #pragma unroll
    for (int mi = 0; mi < 4; mi++) {
        #pragma unroll
        for (int nsub = 0; nsub < 8; nsub++) {
            int n = n0 + wn*64 + nsub*8 + tig*2;
            float b0 = (n < NPIX)   ? qlb[n] + klb[n]     : 0.f;
            float b1 = (n+1 < NPIX) ? qlb[n+1] + klb[n+1] : 0.f;
            #pragma unroll
            for (int half = 0; half < 2; half++) {
                size_t m = m0 + wm*64 + mi*16 + g + half*8;
                float2 o;
                o.x = tf32r(eluf(acc[mi][nsub][2*half]   + b0));
                o.y = tf32r(eluf(acc[mi][nsub][2*half+1] + b1));
                *(float2*)(g_A + m*KPAD + n) = o;
            }
        }
    }
}

// ---------------- main GEMM (tf32, 128 thr): S = A @ W^T + alb ----------------
__global__ __launch_bounds__(128, 2) void gemm_kernel(const float* __restrict__ alb) {
    extern __shared__ float fsm[];
    int tid = threadIdx.x;
    int lane = tid & 31;
    int wid = tid >> 5;
    int wm = wid & 1, wn = wid >> 1;
    int g = lane >> 2, tig = lane & 3;
    int n0 = blockIdx.x * 128;
    size_t m0 = (size_t)blockIdx.y * 128;

    float acc[4][8][4];
    #pragma unroll
    for (int mi = 0; mi < 4; mi++)
        #pragma unroll
        for (int ni = 0; ni < 8; ni++)
            #pragma unroll
            for (int k = 0; k < 4; k++) acc[mi][ni][k] = 0.f;

    {
        float* b = fsm;
        cp_ftile_t128(b,        g_A,  m0, 0, tid, KPAD);
        cp_ftile_t128(b + FBUF, g_Wf, n0, 0, tid, KPAD);
        CP_COMMIT();
    }
    for (int ch = 0; ch < NCH; ch++) {
        if (ch + 1 < NCH) {
            float* b = fsm + ((ch+1)&1)*G_BUF;
            int kc = (ch+1)*KC;
            cp_ftile_t128(b,        g_A,  m0, kc, tid, KPAD);
            cp_ftile_t128(b + FBUF, g_Wf, n0, kc, tid, KPAD);
            CP_COMMIT();
            CP_WAIT1();
        } else {
            CP_WAIT0();
        }
        __syncthreads();
        const float* sA = fsm + (ch&1)*G_BUF;
        const float* sW = sA + FBUF;
        #pragma unroll
        for (int ks = 0; ks < 4; ks++)
            tf32_step4(sA, sW, ks*8, wm, wn, g, tig, acc);
        __syncthreads();
    }

    #pragma unroll
    for (int mi = 0; mi < 4; mi++) {
        #pragma unroll
        for (int nsub = 0; nsub < 8; nsub++) {
            int n = n0 + wn*64 + nsub*8 + tig*2;
            #pragma unroll
            for (int half = 0; half < 2; half++) {
                size_t m = m0 + wm*64 + mi*16 + g + half*8;
                if (n + 1 < NPIX) {
                    float2 o;
                    o.x = acc[mi][nsub][2*half]   + alb[n];
                    o.y = acc[mi][nsub][2*half+1] + alb[n+1];
                    *(float2*)(g_S + m*NPIX + n) = o;
                } else if (n < NPIX) {
                    g_S[m*NPIX + n] = acc[mi][nsub][2*half] + alb[n];
                }
            }
        }
    }
}

// ---------------- softmax (float4): g_S -> g_P (tf32-rounded, zero-padded) ----------------
__global__ __launch_bounds__(256) void softmax_kernel() {
    size_t row = (size_t)blockIdx.x*8 + (threadIdx.x >> 5);
    int lane = threadIdx.x & 31;
    const float4* S4 = (const float4*)(g_S + row*NPIX);   // 149 float4s
    float* P = g_P + row*KPAD;
    float4 v[5];
    float m = -1e30f;
    #pragma unroll
    for (int i = 0; i < 5; i++) {
        int j = lane + 32*i;
        if (j < 149) {
            v[i] = S4[j];
            m = fmaxf(m, fmaxf(fmaxf(v[i].x, v[i].y), fmaxf(v[i].z, v[i].w)));
        } else {
            v[i].x = v[i].y = v[i].z = v[i].w = -1e30f;
        }
    }
    #pragma unroll
    for (int o = 16; o; o >>= 1) m = fmaxf(m, __shfl_xor_sync(0xffffffffu, m, o));
    float s = 0.f;
    #pragma unroll
    for (int i = 0; i < 5; i++) {
        v[i].x = __expf(v[i].x - m); v[i].y = __expf(v[i].y - m);
        v[i].z = __expf(v[i].z - m); v[i].w = __expf(v[i].w - m);
        if (lane + 32*i < 149) s += v[i].x + v[i].y + v[i].z + v[i].w;
    }
    #pragma unroll
    for (int o = 16; o; o >>= 1) s += __shfl_xor_sync(0xffffffffu, s, o);
    float inv = 1.f / s;
    #pragma unroll
    for (int i = 0; i < 5; i++) {
        int j = lane + 32*i;
        if (j < 149) {
            float4 o;
            o.x = tf32r(v[i].x*inv); o.y = tf32r(v[i].y*inv);
            o.z = tf32r(v[i].z*inv); o.w = tf32r(v[i].w*inv);
            *(float4*)(P + 4*j) = o;
        }
    }
    if (lane < 11) {
        float4 z; z.x = z.y = z.z = z.w = 0.f;
        *(float4*)(P + 596 + 4*lane) = z;
    }
}

// ---------------- E GEMM (tf32): E = P @ Vt^T per bh (fp32 out) ----------------
__global__ __launch_bounds__(256, 2) void e_gemm_kernel() {
    extern __shared__ float fsm[];
    int tid = threadIdx.x;
    int lane = tid & 31;
    int wid = tid >> 5;
    int g = lane >> 2, tig = lane & 3;
    int mt = blockIdx.x;
    int bhid = blockIdx.y;
    int p00 = mt * 128;
    int bb = bhid >> 2, h = bhid & 3;

    float acc[8][4];
    #pragma unroll
    for (int ni = 0; ni < 8; ni++)
        #pragma unroll
        for (int k = 0; k < 4; k++) acc[ni][k] = 0.f;

    auto loadT = [&](float* b, int kc) {
        #pragma unroll
        for (int j = 0; j < 4; j++) {
            int idx = tid + j*256;
            int r = idx >> 3, q = idx & 7;
            int p = p00 + r; if (p > NPIX-1) p = NPIX-1;
            cp16(b + r*SKF + q*4, g_P + ((size_t)bhid*NPIX + p)*KPAD + kc + q*4);
        }
        #pragma unroll
        for (int j = 0; j < 2; j++) {
            int idx = tid + j*256;
            int r = idx >> 3, q = idx & 7;
            cp16(b + FBUF + r*SKF + q*4, g_Vt + ((size_t)bhid*DH + r)*KPAD + kc + q*4);
        }
    };

    loadT(fsm, 0);
    CP_COMMIT();
    for (int ch = 0; ch < NCH; ch++) {
        if (ch + 1 < NCH) {
            loadT(fsm + ((ch+1)&1)*E_BUF, (ch+1)*KC);
            CP_COMMIT();
            CP_WAIT1();
        } else {
            CP_WAIT0();
        }
        __syncthreads();
        const float* sP = fsm + (ch&1)*E_BUF;
        const float* sV = sP + FBUF;
        #pragma unroll
        for (int ks = 0; ks < 4; ks++) {
            int ko = ks*8;
            float af[4];
            const float* ar = sP + (wid*16 + g)*SKF + ko + tig;
            af[0] = ar[0];
            af[1] = ar[8*SKF];
            af[2] = ar[4];
            af[3] = ar[8*SKF + 4];
            #pragma unroll
            for (int nsub = 0; nsub < 8; nsub++) {
                const float* br = sV + (nsub*8 + g)*SKF + ko + tig;
                mma_tf32(acc[nsub], af, br[0], br[4]);
            }
        }
        __syncthreads();
    }

    #pragma unroll
    for (int nsub = 0; nsub < 8; nsub++) {
        int d = nsub*8 + tig*2;
        #pragma unroll
        for (int half = 0; half < 2; half++) {
            int p = p00 + wid*16 + g + half*8;
            if (p < NPIX) {
                float2 o; o.x = acc[nsub][2*half]; o.y = acc[nsub][2*half+1];
                *(float2*)(g_E + ((size_t)bb*NPIX + p)*256 + h*DH + d) = o;
            }
        }
    }
}

// ---------------- lin1 GEMM (tf32, 3-term split): F = relu(E @ W1t^T + b) ----------------
__global__ __launch_bounds__(256, 2) void lin1_gemm_kernel(const float* __restrict__ b1) {
    extern __shared__ float fsm[];
    int tid = threadIdx.x;
    int lane = tid & 31;
    int wid = tid >> 5;
    int g = lane >> 2, tig = lane & 3;
    size_t m0 = (size_t)blockIdx.x * 128;

    float acc[8][4];
    #pragma unroll
    for (int ni = 0; ni < 8; ni++)
        #pragma unroll
        for (int k = 0; k < 4; k++) acc[ni][k] = 0.f;

    auto loadT = [&](float* b, int kc) {
        #pragma unroll
        for (int j = 0; j < 4; j++) {
            int idx = tid + j*256;
            int r = idx >> 3, q = idx & 7;
            cp16(b + r*SKF + q*4, g_E + (m0 + r)*256 + kc + q*4);
        }
        #pragma unroll
        for (int j = 0; j < 2; j++) {
            int idx = tid + j*256;
            int r = idx >> 3, q = idx & 7;
            cp16(b + FBUF + r*SKF + q*4, g_W1t + r*256 + kc + q*4);
        }
    };

    loadT(fsm, 0);
    CP_COMMIT();
    for (int ch = 0; ch < NCH1; ch++) {
        if (ch + 1 < NCH1) {
            loadT(fsm + ((ch+1)&1)*E_BUF, (ch+1)*KC);
            CP_COMMIT();
            CP_WAIT1();
        } else {
            CP_WAIT0();
        }
        __syncthreads();
        const float* sE = fsm + (ch&1)*E_BUF;
        const float* sW = sE + FBUF;
        #pragma unroll
        for (int ks = 0; ks < 4; ks++) {
            int ko = ks*8;
            float raw[4], eh[4], el[4];
            const float* ar = sE + (wid*16 + g)*SKF + ko + tig;
            raw[0] = ar[0];
            raw[1] = ar[8*SKF];
            raw[2] = ar[4];
            raw[3] = ar[8*SKF + 4];
            #pragma unroll
            for (int q = 0; q < 4; q++) {
                eh[q] = tf32r(raw[q]);
                el[q] = tf32r(raw[q] - eh[q]);
            }
            #pragma unroll
            for (int nsub = 0; nsub < 8; nsub++) {
                const float* br = sW + (nsub*8 + g)*SKF + ko + tig;
                float w0 = br[0], w1 = br[4];
                float wh0 = tf32r(w0), wh1 = tf32r(w1);
                float wl0 = tf32r(w0 - wh0), wl1 = tf32r(w1 - wh1);
                mma_tf32(acc[nsub], eh, wh0, wh1);
                mma_tf32(acc[nsub], eh, wl0, wl1);
                mma_tf32(acc[nsub], el, wh0, wh1);
            }
        }
        __syncthreads();
    }

    #pragma unroll
    for (int nsub = 0; nsub < 8; nsub++) {
        int d = nsub*8 + tig*2;
        float bb0 = b1[d], bb1 = b1[d+1];
        #pragma unroll
        for (int half = 0; half < 2; half++) {
            size_t m = m0 + wid*16 + g + half*8;
            float2 o;
            o.x = fmaxf(acc[nsub][2*half]   + bb0, 0.f);
            o.y = fmaxf(acc[nsub][2*half+1] + bb1, 0.f);
            *(float2*)(g_F + m*DH + d) = o;
        }
    }
}

// ---------------- LN2 stats ----------------
__global__ void ln2_stats_kernel() {
    int bb = blockIdx.x;
    const float4* base = (const float4*)(g_F + bb*NPIX*DH);
    const int n4 = NPIX*DH/4;
    float s = 0.f, ss = 0.f;
    for (int i = threadIdx.x; i < n4; i += blockDim.x) {
        float4 v = base[i];
        s  += v.x + v.y + v.z + v.w;
        ss += v.x*v.x + v.y*v.y + v.z*v.z + v.w*v.w;
    }
    __shared__ double sh[256], sh2[256];
    sh[threadIdx.x] = (double)s; sh2[threadIdx.x] = (double)ss; __syncthreads();
    for (int o = 128; o; o >>= 1) {
        if (threadIdx.x < o) { sh[threadIdx.x] += sh[threadIdx.x+o]; sh2[threadIdx.x] += sh2[threadIdx.x+o]; }
        __syncthreads();
    }
    if (threadIdx.x == 0) {
        const int n = NPIX*DH;
        double m = sh[0] / (double)n;
        double var = sh2[0] / (double)n - m*m;
        g_mu2[bb] = (float)m;
        g_rv2[bb] = (float)(1.0 / sqrt(var + 1e-5));
    }
}

// ---------------- LN2 apply + max ----------------
__global__ void ln2max_kernel() {
    int bb = blockIdx.x;
    int d = threadIdx.x & 63, pc = threadIdx.x >> 6;
    float mu = g_mu2[bb], rv = g_rv2[bb];
    float m = -1e30f;
    for (int p = pc; p < NPIX; p += 4) {
        float v = (g_F[(bb*NPIX + p)*DH + d] - mu) * rv;
        m = fmaxf(m, v);
    }
    __shared__ float sh[256];
    sh[threadIdx.x] = m; __syncthreads();
    if (pc == 0) {
        m = fmaxf(fmaxf(sh[d], sh[64+d]), fmaxf(sh[128+d], sh[192+d]));
        g_M[bb*DH + d] = m;
    }
}

// ---------------- final lin2 + elu ----------------
__global__ void final_kernel(const float* __restrict__ w, const float* __restrict__ b,
                             float* __restrict__ out) {
    int idx = blockIdx.x * blockDim.x + threadIdx.x;
    if (idx >= NB*10) return;
    int bb = idx / 10, j = idx % 10;
    float acc = b[j];
    #pragma unroll
    for (int d = 0; d < DH; d++) acc += g_M[bb*DH + d] * w[d*10 + j];
    out[idx] = eluf(acc);
}

extern "C" void kernel_launch(void* const* d_in, const int* in_sizes, int n_in,
                              void* d_out, int out_size) {
    const float* x       = (const float*)d_in[0];
    const float* conv1_w = (const float*)d_in[1];
    const float* conv1_b = (const float*)d_in[2];
    const float* conv2_w = (const float*)d_in[3];
    const float* conv2_b = (const float*)d_in[4];
    const float* kp_w    = (const float*)d_in[5];
    const float* kp_b    = (const float*)d_in[6];
    const float* qp_w    = (const float*)d_in[7];
    const float* qp_b    = (const float*)d_in[8];
    const float* vp_w    = (const float*)d_in[9];
    const float* vp_b    = (const float*)d_in[10];
    const float* klin_w  = (const float*)d_in[11];
    const float* klin_b  = (const float*)d_in[12];
    const float* qlin_w  = (const float*)d_in[13];
    const float* qlin_b  = (const float*)d_in[14];
    const float* alin_w  = (const float*)d_in[15];
    const float* alin_b  = (const float*)d_in[16];
    const float* knorm_g = (const float*)d_in[17];
    const float* knorm_b = (const float*)d_in[18];
    const float* qnorm_g = (const float*)d_in[19];
    const float* qnorm_b = (const float*)d_in[20];
    const float* vnorm_g = (const float*)d_in[21];
    const float* vnorm_b = (const float*)d_in[22];
    const float* lin1_w  = (const float*)d_in[23];
    const float* lin1_b  = (const float*)d_in[24];
    const float* lin2_w  = (const float*)d_in[25];
    const float* lin2_b  = (const float*)d_in[26];
    float* out = (float*)d_out;

    cudaFuncSetAttribute(logits_gemm_kernel, cudaFuncAttributeMaxDynamicSharedMemorySize, GEMM_SMEM);
    cudaFuncSetAttribute(gemm_kernel,        cudaFuncAttributeMaxDynamicSharedMemorySize, GEMM_SMEM);
    cudaFuncSetAttribute(e_gemm_kernel,      cudaFuncAttributeMaxDynamicSharedMemorySize, EGEMM_SMEM);
    cudaFuncSetAttribute(lin1_gemm_kernel,   cudaFuncAttributeMaxDynamicSharedMemorySize, EGEMM_SMEM);
    cudaFuncSetAttribute(proj_gemm_kernel,   cudaFuncAttributeMaxDynamicSharedMemorySize, EGEMM_SMEM);

    conv1_kernel<<<(NB*16*150*5 + 255)/256, 256>>>(x, conv1_w, conv1_b);
    conv2_feats_kernel<<<(EROWS*64 + 255)/256, 256>>>(conv2_w, conv2_b);
    prep_all_kernel<<<(PREP_TOT + 255)/256, 256>>>(alin_w, qlin_w, klin_w, lin1_w,
                                                   kp_w, qp_w, vp_w);
    {
        dim3 g(EROWS/128, 12);                     // (298, 12)
        proj_gemm_kernel<<<g, 256, EGEMM_SMEM>>>(kp_b, qp_b, vp_b);
    }
    {
        dim3 g(NB, 3);
        ln_stats_kernel<<<g, 512>>>();
    }
    {
        dim3 g(PER_B/1024, NB, 3);
        ln_apply_kernel<<<g, 256>>>(knorm_g, knorm_b, qnorm_g, qnorm_b, vnorm_g, vnorm_b);
    }
    {
        dim3 g(KPAD/128, MROWS/128);               // (5, 1192)
        logits_gemm_kernel<<<g, 128, GEMM_SMEM>>>(qlin_b, klin_b);
    }
    {
        dim3 g(KPAD/128, MROWS/128);               // (5, 1192)
        gemm_kernel<<<g, 128, GEMM_SMEM>>>(alin_b);
    }
    vtrans_kernel<<<NB*HEADS, 256>>>();
    softmax_kernel<<<MROWS/8, 256>>>();
    {
        dim3 g(5, NB*HEADS);                       // (5, 256)
        e_gemm_kernel<<<g, 256, EGEMM_SMEM>>>();
    }
    lin1_gemm_kernel<<<EROWS/128, 256, EGEMM_SMEM>>>(lin1_b);
    ln2_stats_kernel<<<NB, 256>>>();
    ln2max_kernel<<<NB, 256>>>();
    final_kernel<<<3, 256>>>(lin2_w, lin2_b, out);
}

// round 13
// speedup vs baseline: 1.2956x; 1.1827x over previous
#include <cuda_runtime.h>
#include <cuda_bf16.h>
#include <math.h>
#include <stdint.h>

#define NB 64
#define NPIX 596
#define HEADS 4
#define DH 64
#define PER_B (HEADS*NPIX*DH)   // 152576
#define MROWS (NB*HEADS*NPIX)   // 152576
#define EROWS (NB*NPIX)         // 38144
#define KPAD 640

// ---- tf32 gemm common ----
#define KC 32
#define NCH (KPAD/KC)           // 20
#define NCHL (128/KC)           // 4
#define NCH1 (256/KC)           // 8
#define NCHP (64/KC)            // 2
#define SKF 36
#define FBUF (128*SKF)
#define VFBUF (64*SKF)
#define G_BUF (2*FBUF)
#define GEMM_SMEM (2*G_BUF*4)                   // 73728
#define E_BUF (FBUF + VFBUF)
#define EGEMM_SMEM (2*E_BUF*4)                  // 55296
#define E3_BUF (FBUF + 2*VFBUF)                 // E + Wh + Wl
#define E3GEMM_SMEM (2*E3_BUF*4)                // 73728
#define C2_BUF (FBUF + 2*32*SKF)
#define C2GEMM_SMEM (2*C2_BUF*4)                // 55296

// ---------------- scratch ----------------
__device__ float g_conv1[NB*16*150*5];
__device__ float g_col[(size_t)EROWS*64];       // im2col for conv2
__device__ float g_feats[(size_t)EROWS*64];     // [b*p][64] zero-padded feats
__device__ float g_K[NB*HEADS*NPIX*DH];
__device__ float g_Q[NB*HEADS*NPIX*DH];
__device__ float g_V[NB*HEADS*NPIX*DH];
__device__ float g_Wkqvh[768*64], g_Wkqvl[768*64];
__device__ float g_Wc2h[32*64],  g_Wc2l[32*64];
__device__ float g_W1th[64*256], g_W1tl[64*256];
__device__ float g_mu[3*NB], g_rv[3*NB];
__device__ float g_QKf[(size_t)MROWS*128];
__device__ float g_Wqkf[(size_t)KPAD*128];
__device__ float g_A[(size_t)MROWS*KPAD];
__device__ float g_Wf[(size_t)KPAD*KPAD];
__device__ float g_Vt[(size_t)NB*HEADS*DH*KPAD];
__device__ float g_S[(size_t)MROWS*NPIX];
__device__ float g_P[(size_t)MROWS*KPAD];
__device__ float g_E[(size_t)EROWS*256];
__device__ float g_F[EROWS*DH];
__device__ float g_mu2[NB], g_rv2[NB];
__device__ float g_M[NB*DH];

__device__ __forceinline__ float eluf(float x) {
    return x > 0.f ? x : (__expf(x) - 1.f);
}
__device__ __forceinline__ float tf32r(float x) {
    uint32_t u;
    asm("cvt.rna.tf32.f32 %0, %1;" : "=r"(u) : "f"(x));
    return __uint_as_float(u);
}

// ---- mma.sync tf32 ----
__device__ __forceinline__ void mma_tf32(float* c, const float* a, float b0, float b1) {
    asm volatile(
        "mma.sync.aligned.m16n8k8.row.col.f32.tf32.tf32.f32 "
        "{%0,%1,%2,%3}, {%4,%5,%6,%7}, {%8,%9}, {%0,%1,%2,%3};"
        : "+f"(c[0]), "+f"(c[1]), "+f"(c[2]), "+f"(c[3])
        : "r"(__float_as_uint(a[0])), "r"(__float_as_uint(a[1])),
          "r"(__float_as_uint(a[2])), "r"(__float_as_uint(a[3])),
          "r"(__float_as_uint(b0)), "r"(__float_as_uint(b1)));
}
// ---- cp.async ----
__device__ __forceinline__ void cp16(void* smem, const void* gmem) {
    uint32_t s = (uint32_t)__cvta_generic_to_shared(smem);
    asm volatile("cp.async.cg.shared.global [%0], [%1], 16;" :: "r"(s), "l"(gmem));
}
#define CP_COMMIT() asm volatile("cp.async.commit_group;" ::: "memory")
#define CP_WAIT1()  asm volatile("cp.async.wait_group 1;" ::: "memory")
#define CP_WAIT0()  asm volatile("cp.async.wait_group 0;" ::: "memory")

// ---------------- conv1 + relu ----------------
__global__ void conv1_kernel(const float* __restrict__ x,
                             const float* __restrict__ w,
                             const float* __restrict__ b) {
    int idx = blockIdx.x * blockDim.x + threadIdx.x;
    if (idx >= NB*16*150*5) return;
    int ow = idx % 5;
    int oh = (idx / 5) % 150;
    int co = (idx / (5*150)) % 16;
    int bb = idx / (5*150*16);
    float acc = b[co];
    #pragma unroll
    for (int ci = 0; ci < 4; ci++)
        #pragma unroll
        for (int kh = 0; kh < 2; kh++)
            #pragma unroll
            for (int kw = 0; kw < 2; kw++)
                acc += x[((bb*4+ci)*151 + oh+kh)*6 + ow+kw] *
                       w[((co*4+ci)*2 + kh)*2 + kw];
    g_conv1[idx] = fmaxf(acc, 0.f);
}

// ---------------- im2col for conv2: col[bp][ci*4+kh*2+kw] ----------------
__global__ void im2col_kernel() {
    int idx = blockIdx.x * blockDim.x + threadIdx.x;
    if (idx >= EROWS*64) return;
    int c = idx & 63;
    int bp = idx >> 6;
    int p = bp % NPIX, bb = bp / NPIX;
    int oh = p / 4, ow = p % 4;
    int ci = c >> 2, kh = (c >> 1) & 1, kw = c & 1;
    g_col[idx] = g_conv1[((bb*16+ci)*150 + oh+kh)*5 + ow+kw];
}

// ---------------- coords + zero-pad fill for feats cols 32..63 ----------------
__global__ void coords_kernel() {
    int idx = blockIdx.x * blockDim.x + threadIdx.x;
    if (idx >= EROWS*32) return;
    int c = 32 + (idx & 31);
    int bp = idx >> 5;
    int p = bp % NPIX;
    float v = 0.f;
    if (c == 32) v = (float)(p % 4) / 4.f;
    else if (c == 33) v = (float)(p / 4) / 149.f;
    g_feats[(size_t)bp*64 + c] = v;
}

// ---------------- conv2 GEMM (tf32 3-term, pre-split W): feats[:, :32] ----------------
__global__ __launch_bounds__(256, 2) void conv2_gemm_kernel(const float* __restrict__ b2) {
    extern __shared__ float fsm[];
    int tid = threadIdx.x;
    int lane = tid & 31;
    int wid = tid >> 5;
    int g = lane >> 2, tig = lane & 3;
    size_t m0 = (size_t)blockIdx.x * 128;

    float acc[4][4];
    #pragma unroll
    for (int ni = 0; ni < 4; ni++)
        #pragma unroll
        for (int k = 0; k < 4; k++) acc[ni][k] = 0.f;

    auto loadT = [&](float* b, int kc) {
        #pragma unroll
        for (int j = 0; j < 4; j++) {
            int idx = tid + j*256;
            int r = idx >> 3, q = idx & 7;
            cp16(b + r*SKF + q*4, g_col + (m0 + r)*64 + kc + q*4);
        }
        {
            int r = tid >> 3, q = tid & 7;   // 256 thr = 32 rows x 8q
            cp16(b + FBUF + r*SKF + q*4, g_Wc2h + r*64 + kc + q*4);
            cp16(b + FBUF + 32*SKF + r*SKF + q*4, g_Wc2l + r*64 + kc + q*4);
        }
    };

    loadT(fsm, 0);
    CP_COMMIT();
    for (int ch = 0; ch < NCHP; ch++) {
        if (ch + 1 < NCHP) {
            loadT(fsm + ((ch+1)&1)*C2_BUF, (ch+1)*KC);
            CP_COMMIT();
            CP_WAIT1();
        } else {
            CP_WAIT0();
        }
        __syncthreads();
        const float* sE = fsm + (ch&1)*C2_BUF;
        const float* sWh = sE + FBUF;
        const float* sWl = sWh + 32*SKF;
        #pragma unroll
        for (int ks = 0; ks < 4; ks++) {
            int ko = ks*8;
            float raw[4], eh[4], el[4];
            const float* ar = sE + (wid*16 + g)*SKF + ko + tig;
            raw[0] = ar[0];
            raw[1] = ar[8*SKF];
            raw[2] = ar[4];
            raw[3] = ar[8*SKF + 4];
            #pragma unroll
            for (int q = 0; q < 4; q++) {
                eh[q] = tf32r(raw[q]);
                el[q] = tf32r(raw[q] - eh[q]);
            }
            #pragma unroll
            for (int nsub = 0; nsub < 4; nsub++) {
                const float* bh = sWh + (nsub*8 + g)*SKF + ko + tig;
                const float* bl = sWl + (nsub*8 + g)*SKF + ko + tig;
                float wh0 = bh[0], wh1 = bh[4];
                float wl0 = bl[0], wl1 = bl[4];
                mma_tf32(acc[nsub], eh, wh0, wh1);
                mma_tf32(acc[nsub], eh, wl0, wl1);
                mma_tf32(acc[nsub], el, wh0, wh1);
            }
        }
        __syncthreads();
    }

    #pragma unroll
    for (int nsub = 0; nsub < 4; nsub++) {
        int n = nsub*8 + tig*2;
        float b0 = b2[n], b1 = b2[n+1];
        #pragma unroll
        for (int half = 0; half < 2; half++) {
            size_t m = m0 + wid*16 + g + half*8;
            float2 o;
            o.x = fmaxf(acc[nsub][2*half]   + b0, 0.f);
            o.y = fmaxf(acc[nsub][2*half+1] + b1, 0.f);
            *(float2*)(g_feats + m*64 + n) = o;
        }
    }
}

// ---------------- proj GEMM (tf32 3-term, pre-split W): [K|Q|V] ----------------
__global__ __launch_bounds__(256, 2) void proj_gemm_kernel(
    const float* __restrict__ kb, const float* __restrict__ qb,
    const float* __restrict__ vb) {
    extern __shared__ float fsm[];
    int tid = threadIdx.x;
    int lane = tid & 31;
    int wid = tid >> 5;
    int g = lane >> 2, tig = lane & 3;
    size_t m0 = (size_t)blockIdx.x * 128;
    int n0 = blockIdx.y * 64;

    float acc[8][4];
    #pragma unroll
    for (int ni = 0; ni < 8; ni++)
        #pragma unroll
        for (int k = 0; k < 4; k++) acc[ni][k] = 0.f;

    auto loadT = [&](float* b, int kc) {
        #pragma unroll
        for (int j = 0; j < 4; j++) {
            int idx = tid + j*256;
            int r = idx >> 3, q = idx & 7;
            cp16(b + r*SKF + q*4, g_feats + (m0 + r)*64 + kc + q*4);
        }
        #pragma unroll
        for (int j = 0; j < 2; j++) {
            int idx = tid + j*256;
            int r = idx >> 3, q = idx & 7;
            cp16(b + FBUF + r*SKF + q*4, g_Wkqvh + (n0 + r)*64 + kc + q*4);
            cp16(b + FBUF + VFBUF + r*SKF + q*4, g_Wkqvl + (n0 + r)*64 + kc + q*4);
        }
    };

    loadT(fsm, 0);
    CP_COMMIT();
    for (int ch = 0; ch < NCHP; ch++) {
        if (ch + 1 < NCHP) {
            loadT(fsm + ((ch+1)&1)*E3_BUF, (ch+1)*KC);
            CP_COMMIT();
            CP_WAIT1();
        } else {
            CP_WAIT0();
        }
        __syncthreads();
        const float* sE = fsm + (ch&1)*E3_BUF;
        const float* sWh = sE + FBUF;
        const float* sWl = sWh + VFBUF;
        #pragma unroll
        for (int ks = 0; ks < 4; ks++) {
            int ko = ks*8;
            float raw[4], eh[4], el[4];
            const float* ar = sE + (wid*16 + g)*SKF + ko + tig;
            raw[0] = ar[0];
            raw[1] = ar[8*SKF];
            raw[2] = ar[4];
            raw[3] = ar[8*SKF + 4];
            #pragma unroll
            for (int q = 0; q < 4; q++) {
                eh[q] = tf32r(raw[q]);
                el[q] = tf32r(raw[q] - eh[q]);
            }
            #pragma unroll
            for (int nsub = 0; nsub < 8; nsub++) {
                const float* bh = sWh + (nsub*8 + g)*SKF + ko + tig;
                const float* bl = sWl + (nsub*8 + g)*SKF + ko + tig;
                float wh0 = bh[0], wh1 = bh[4];
                float wl0 = bl[0], wl1 = bl[4];
                mma_tf32(acc[nsub], eh, wh0, wh1);
                mma_tf32(acc[nsub], eh, wl0, wl1);
                mma_tf32(acc[nsub], el, wh0, wh1);
            }
        }
        __syncthreads();
    }

    int mloc[2], bbv[2], pv[2];
    #pragma unroll
    for (int half = 0; half < 2; half++) {
        mloc[half] = (int)(m0 + wid*16 + g + half*8);
        bbv[half] = mloc[half] / NPIX;
        pv[half]  = mloc[half] % NPIX;
    }
    #pragma unroll
    for (int nsub = 0; nsub < 8; nsub++) {
        int n = n0 + nsub*8 + tig*2;       // 0..767
        int t = n >> 8;
        int hd = n & 255;
        int h = hd >> 6, d = hd & 63;
        const float* B = t == 0 ? kb : t == 1 ? qb : vb;
        float* O = t == 0 ? g_K : t == 1 ? g_Q : g_V;
        float b0 = B[hd], b1 = B[hd+1];
        #pragma unroll
        for (int half = 0; half < 2; half++) {
            float2 o;
            o.x = acc[nsub][2*half]   + b0;
            o.y = acc[nsub][2*half+1] + b1;
            *(float2*)(O + ((size_t)(bbv[half]*HEADS + h)*NPIX + pv[half])*DH + d) = o;
        }
    }
}

// ---------------- LN stats (512 thr, float4) ----------------
__global__ __launch_bounds__(512) void ln_stats_kernel() {
    int bb = blockIdx.x, t = blockIdx.y;
    const float4* base = (const float4*)((t==0 ? g_K : t==1 ? g_Q : g_V) + bb*PER_B);
    const int n4 = PER_B/4;
    float s = 0.f, ss = 0.f;
    for (int i = threadIdx.x; i < n4; i += 512) {
        float4 v = base[i];
        s  += v.x + v.y + v.z + v.w;
        ss += v.x*v.x + v.y*v.y + v.z*v.z + v.w*v.w;
    }
    __shared__ double sh[512], sh2[512];
    sh[threadIdx.x] = (double)s; sh2[threadIdx.x] = (double)ss; __syncthreads();
    for (int o = 256; o; o >>= 1) {
        if (threadIdx.x < o) { sh[threadIdx.x] += sh[threadIdx.x+o]; sh2[threadIdx.x] += sh2[threadIdx.x+o]; }
        __syncthreads();
    }
    if (threadIdx.x == 0) {
        double m = sh[0] / (double)PER_B;
        double var = sh2[0] / (double)PER_B - m*m;
        g_mu[t*NB+bb] = (float)m;
        g_rv[t*NB+bb] = (float)(1.0 / sqrt(var + 1e-5));
    }
}

// ---------------- LN apply: Q,K -> tf32-rounded QK concat; V -> fp32 ----------------
__global__ void ln_apply_kernel(const float* __restrict__ kg, const float* __restrict__ kb,
                                const float* __restrict__ qg, const float* __restrict__ qb,
                                const float* __restrict__ vg, const float* __restrict__ vb) {
    int t = blockIdx.z;
    int bb = blockIdx.y;
    const float* base = (t==0 ? g_K : t==1 ? g_Q : g_V) + bb*PER_B;
    const float* g = t==0 ? kg : t==1 ? qg : vg;
    const float* be = t==0 ? kb : t==1 ? qb : vb;
    int off = (blockIdx.x*256 + threadIdx.x)*4;
    float mu = g_mu[t*NB+bb], rv = g_rv[t*NB+bb];
    float4 v  = *(const float4*)(base + off);
    float4 gg = *(const float4*)(g + off);
    float4 bv = *(const float4*)(be + off);
    float4 r;
    r.x = (v.x - mu)*rv*gg.x + bv.x;
    r.y = (v.y - mu)*rv*gg.y + bv.y;
    r.z = (v.z - mu)*rv*gg.z + bv.z;
    r.w = (v.w - mu)*rv*gg.w + bv.w;
    if (t == 2) {
        *(float4*)(g_V + bb*PER_B + off) = r;
    } else {
        int d = off & 63;
        int hp = off >> 6;
        size_t row = (size_t)bb*HEADS*NPIX + hp;
        int col = d + (t == 0 ? 64 : 0);
        float4 o;
        o.x = tf32r(r.x); o.y = tf32r(r.y); o.z = tf32r(r.z); o.w = tf32r(r.w);
        *(float4*)(g_QKf + row*128 + col) = o;
    }
}

// ---------------- V transpose (tf32-rounded): Vt[bh][d][p_pad] ----------------
__global__ void vtrans_kernel() {
    __shared__ float tile[32][65];
    int bhid = blockIdx.x;
    const float* Vb = g_V + (size_t)bhid*NPIX*DH;
    int t = threadIdx.x;
    for (int pt = 0; pt < 20; pt++) {
        int p0 = pt*32;
        for (int i = t; i < 32*64; i += 256) {
            int r = i >> 6, c = i & 63;
            tile[r][c] = (p0 + r < NPIX) ? Vb[(p0 + r)*DH + c] : 0.f;
        }
        __syncthreads();
        for (int i = t; i < 64*32; i += 256) {
            int d = i >> 5, pp = i & 31;
            g_Vt[((size_t)bhid*DH + d)*KPAD + p0 + pp] = tf32r(tile[pp][d]);
        }
        __syncthreads();
    }
}

// ---------------- merged weight prep ----------------
__global__ void prep_all_kernel(const float* __restrict__ alw,
                                const float* __restrict__ qlw,
                                const float* __restrict__ klw,
                                const float* __restrict__ w1,
                                const float* __restrict__ kpw,
                                const float* __restrict__ qpw,
                                const float* __restrict__ vpw,
                                const float* __restrict__ c2w) {
    int idx = blockIdx.x*256 + threadIdx.x;
    if (idx < KPAD*KPAD) {
        int k = idx / KPAD, n = idx % KPAD;
        float v = (k < NPIX && n < NPIX) ? alw[k*NPIX + n] : 0.f;
        g_Wf[(size_t)n*KPAD + k] = tf32r(v);
        return;
    }
    idx -= KPAD*KPAD;
    if (idx < KPAD*128) {
        int n = idx >> 7, k = idx & 127;
        float v = 0.f;
        if (n < NPIX) v = (k < 64) ? qlw[k*NPIX + n] : klw[(k-64)*NPIX + n];
        g_Wqkf[(size_t)n*128 + k] = tf32r(v);
        return;
    }
    idx -= KPAD*128;
    if (idx < 64*256) {
        int d = idx >> 8, c = idx & 255;
        float v = w1[c*64 + d];
        float h = tf32r(v);
        g_W1th[d*256 + c] = h;
        g_W1tl[d*256 + c] = tf32r(v - h);
        return;
    }
    idx -= 64*256;
    if (idx < 768*64) {
        int n = idx >> 6, c = idx & 63;
        int t = n >> 8, hd = n & 255;
        const float* W = t == 0 ? kpw : t == 1 ? qpw : vpw;
        float v = (c < 34) ? W[c*256 + hd] : 0.f;
        float h = tf32r(v);
        g_Wkqvh[n*64 + c] = h;
        g_Wkqvl[n*64 + c] = tf32r(v - h);
        return;
    }
    idx -= 768*64;
    if (idx < 32*64) {
        int n = idx >> 6, c = idx & 63;
        int ci = c >> 2, kh = (c >> 1) & 1, kw = c & 1;
        float v = c2w[((n*16+ci)*2 + kh)*2 + kw];
        float h = tf32r(v);
        g_Wc2h[n*64 + c] = h;
        g_Wc2l[n*64 + c] = tf32r(v - h);
    }
}
#define PREP_TOT (KPAD*KPAD + KPAD*128 + 64*256 + 768*64 + 32*64)

// ---------------- pipelined cp.async tile loaders (fp32, 128 thr) ----------------
__device__ __forceinline__ void cp_ftile_t128(float* dst, const float* g,
                                              size_t row0, int kc, int tid, int gstride) {
    #pragma unroll
    for (int j = 0; j < 8; j++) {
        int idx = tid + j*128;
        int r = idx >> 3, q = idx & 7;
        cp16(dst + r*SKF + q*4, g + (row0 + r)*(size_t)gstride + kc + q*4);
    }
}

// ---------------- tf32 GEMM inner step: 4 warps, warp tile 64x64 ----------------
__device__ __forceinline__ void tf32_step4(const float* sA, const float* sW, int ko,
                                           int wm, int wn, int g, int tig,
                                           float acc[4][8][4]) {
    float af[4][4];
    #pragma unroll
    for (int mi = 0; mi < 4; mi++) {
        const float* ar = sA + (wm*64 + mi*16 + g)*SKF + ko + tig;
        af[mi][0] = ar[0];
        af[mi][1] = ar[8*SKF];
        af[mi][2] = ar[4];
        af[mi][3] = ar[8*SKF + 4];
    }
    #pragma unroll
    for (int nsub = 0; nsub < 8; nsub++) {
        const float* br = sW + (wn*64 + nsub*8 + g)*SKF + ko + tig;
        float b0 = br[0], b1 = br[4];
        #pragma unroll
        for (int mi = 0; mi < 4; mi++)
            mma_tf32(acc[mi][nsub], af[mi], b0, b1);
    }
}

// ---------------- logits GEMM (tf32, 128 thr): A = elu(QK @ Wqk^T + bias) ----------------
__global__ __launch_bounds__(128, 2) void logits_gemm_kernel(
    const float* __restrict__ qlb, const float* __restrict__ klb) {
    extern __shared__ float fsm[];
    int tid = threadIdx.x;
    int lane = tid & 31;
    int wid = tid >> 5;
    int wm = wid & 1, wn = wid >> 1;
    int g = lane >> 2, tig = lane & 3;
    int n0 = blockIdx.x * 128;
    size_t m0 = (size_t)blockIdx.y * 128;

    float acc[4][8][4];
    #pragma unroll
    for (int mi = 0; mi < 4; mi++)
        #pragma unroll
        for (int ni = 0; ni < 8; ni++)
            #pragma unroll
            for (int k = 0; k < 4; k++) acc[mi][ni][k] = 0.f;

    {
        float* b = fsm;
        cp_ftile_t128(b,        g_QKf,  m0, 0, tid, 128);
        cp_ftile_t128(b + FBUF, g_Wqkf, n0, 0, tid, 128);
        CP_COMMIT();
    }
    for (int ch = 0; ch < NCHL; ch++) {
        if (ch + 1 < NCHL) {
            float* b = fsm + ((ch+1)&1)*G_BUF;
            int kc = (ch+1)*KC;
            cp_ftile_t128(b,        g_QKf,  m0, kc, tid, 128);
            cp_ftile_t128(b + FBUF, g_Wqkf, n0, kc, tid, 128);
            CP_COMMIT();
            CP_WAIT1();
        } else {
            CP_WAIT0();
        }
        __syncthreads();
        const float* sA = fsm + (ch&1)*G_BUF;
        const float* sW = sA + FBUF;
        #pragma unroll
        for (int ks = 0; ks < 4; ks++)
            tf32_step4(sA, sW, ks*8, wm, wn, g, tig, acc);
        __syncthreads();
    }

    #pragma unroll
    for (int mi = 0; mi < 4; mi++) {
        #pragma unroll
        for (int nsub = 0; nsub < 8; nsub++) {
            int n = n0 + wn*64 + nsub*8 + tig*2;
            float b0 = (n < NPIX)   ? qlb[n] + klb[n]     : 0.f;
            float b1 = (n+1 < NPIX) ? qlb[n+1] + klb[n+1] : 0.f;
            #pragma unroll
            for (int half = 0; half < 2; half++) {
                size_t m = m0 + wm*64 + mi*16 + g + half*8;
                float2 o;
                o.x = tf32r(eluf(acc[mi][nsub][2*half]   + b0));
                o.y = tf32r(eluf(acc[mi][nsub][2*half+1] + b1));
                *(float2*)(g_A + m*KPAD + n) = o;
            }
        }
    }
}

// ---------------- main GEMM (tf32, 128 thr): S = A @ W^T + alb ----------------
__global__ __launch_bounds__(128, 2) void gemm_kernel(const float* __restrict__ alb) {
    extern __shared__ float fsm[];
    int tid = threadIdx.x;
    int lane = tid & 31;
    int wid = tid >> 5;
    int wm = wid & 1, wn = wid >> 1;
    int g = lane >> 2, tig = lane & 3;
    int n0 = blockIdx.x * 128;
    size_t m0 = (size_t)blockIdx.y * 128;

    float acc[4][8][4];
    #pragma unroll
    for (int mi = 0; mi < 4; mi++)
        #pragma unroll
        for (int ni = 0; ni < 8; ni++)
            #pragma unroll
            for (int k = 0; k < 4; k++) acc[mi][ni][k] = 0.f;

    {
        float* b = fsm;
        cp_ftile_t128(b,        g_A,  m0, 0, tid, KPAD);
        cp_ftile_t128(b + FBUF, g_Wf, n0, 0, tid, KPAD);
        CP_COMMIT();
    }
    for (int ch = 0; ch < NCH; ch++) {
        if (ch + 1 < NCH) {
            float* b = fsm + ((ch+1)&1)*G_BUF;
            int kc = (ch+1)*KC;
            cp_ftile_t128(b,        g_A,  m0, kc, tid, KPAD);
            cp_ftile_t128(b + FBUF, g_Wf, n0, kc, tid, KPAD);
            CP_COMMIT();
            CP_WAIT1();
        } else {
            CP_WAIT0();
        }
        __syncthreads();
        const float* sA = fsm + (ch&1)*G_BUF;
        const float* sW = sA + FBUF;
        #pragma unroll
        for (int ks = 0; ks < 4; ks++)
            tf32_step4(sA, sW, ks*8, wm, wn, g, tig, acc);
        __syncthreads();
    }

    #pragma unroll
    for (int mi = 0; mi < 4; mi++) {
        #pragma unroll
        for (int nsub = 0; nsub < 8; nsub++) {
            int n = n0 + wn*64 + nsub*8 + tig*2;
            #pragma unroll
            for (int half = 0; half < 2; half++) {
                size_t m = m0 + wm*64 + mi*16 + g + half*8;
                if (n + 1 < NPIX) {
                    float2 o;
                    o.x = acc[mi][nsub][2*half]   + alb[n];
                    o.y = acc[mi][nsub][2*half+1] + alb[n+1];
                    *(float2*)(g_S + m*NPIX + n) = o;
                } else if (n < NPIX) {
                    g_S[m*NPIX + n] = acc[mi][nsub][2*half] + alb[n];
                }
            }
        }
    }
}

// ---------------- softmax (float4): g_S -> g_P (tf32-rounded, zero-padded) ----------------
__global__ __launch_bounds__(256) void softmax_kernel() {
    size_t row = (size_t)blockIdx.x*8 + (threadIdx.x >> 5);
    int lane = threadIdx.x & 31;
    const float4* S4 = (const float4*)(g_S + row*NPIX);
    float* P = g_P + row*KPAD;
    float4 v[5];
    float m = -1e30f;
    #pragma unroll
    for (int i = 0; i < 5; i++) {
        int j = lane + 32*i;
        if (j < 149) {
            v[i] = S4[j];
            m = fmaxf(m, fmaxf(fmaxf(v[i].x, v[i].y), fmaxf(v[i].z, v[i].w)));
        } else {
            v[i].x = v[i].y = v[i].z = v[i].w = -1e30f;
        }
    }
    #pragma unroll
    for (int o = 16; o; o >>= 1) m = fmaxf(m, __shfl_xor_sync(0xffffffffu, m, o));
    float s = 0.f;
    #pragma unroll
    for (int i = 0; i < 5; i++) {
        v[i].x = __expf(v[i].x - m); v[i].y = __expf(v[i].y - m);
        v[i].z = __expf(v[i].z - m); v[i].w = __expf(v[i].w - m);
        if (lane + 32*i < 149) s += v[i].x + v[i].y + v[i].z + v[i].w;
    }
    #pragma unroll
    for (int o = 16; o; o >>= 1) s += __shfl_xor_sync(0xffffffffu, s, o);
    float inv = 1.f / s;
    #pragma unroll
    for (int i = 0; i < 5; i++) {
        int j = lane + 32*i;
        if (j < 149) {
            float4 o;
            o.x = tf32r(v[i].x*inv); o.y = tf32r(v[i].y*inv);
            o.z = tf32r(v[i].z*inv); o.w = tf32r(v[i].w*inv);
            *(float4*)(P + 4*j) = o;
        }
    }
    if (lane < 11) {
        float4 z; z.x = z.y = z.z = z.w = 0.f;
        *(float4*)(P + 596 + 4*lane) = z;
    }
}

// ---------------- E GEMM (tf32): E = P @ Vt^T per bh (fp32 out) ----------------
__global__ __launch_bounds__(256, 2) void e_gemm_kernel() {
    extern __shared__ float fsm[];
    int tid = threadIdx.x;
    int lane = tid & 31;
    int wid = tid >> 5;
    int g = lane >> 2, tig = lane & 3;
    int mt = blockIdx.x;
    int bhid = blockIdx.y;
    int p00 = mt * 128;
    int bb = bhid >> 2, h = bhid & 3;

    float acc[8][4];
    #pragma unroll
    for (int ni = 0; ni < 8; ni++)
        #pragma unroll
        for (int k = 0; k < 4; k++) acc[ni][k] = 0.f;

    auto loadT = [&](float* b, int kc) {
        #pragma unroll
        for (int j = 0; j < 4; j++) {
            int idx = tid + j*256;
            int r = idx >> 3, q = idx & 7;
            int p = p00 + r; if (p > NPIX-1) p = NPIX-1;
            cp16(b + r*SKF + q*4, g_P + ((size_t)bhid*NPIX + p)*KPAD + kc + q*4);
        }
        #pragma unroll
        for (int j = 0; j < 2; j++) {
            int idx = tid + j*256;
            int r = idx >> 3, q = idx & 7;
            cp16(b + FBUF + r*SKF + q*4, g_Vt + ((size_t)bhid*DH + r)*KPAD + kc + q*4);
        }
    };

    loadT(fsm, 0);
    CP_COMMIT();
    for (int ch = 0; ch < NCH; ch++) {
        if (ch + 1 < NCH) {
            loadT(fsm + ((ch+1)&1)*E_BUF, (ch+1)*KC);
            CP_COMMIT();
            CP_WAIT1();
        } else {
            CP_WAIT0();
        }
        __syncthreads();
        const float* sP = fsm + (ch&1)*E_BUF;
        const float* sV = sP + FBUF;
        #pragma unroll
        for (int ks = 0; ks < 4; ks++) {
            int ko = ks*8;
            float af[4];
            const float* ar = sP + (wid*16 + g)*SKF + ko + tig;
            af[0] = ar[0];
            af[1] = ar[8*SKF];
            af[2] = ar[4];
            af[3] = ar[8*SKF + 4];
            #pragma unroll
            for (int nsub = 0; nsub < 8; nsub++) {
                const float* br = sV + (nsub*8 + g)*SKF + ko + tig;
                mma_tf32(acc[nsub], af, br[0], br[4]);
            }
        }
        __syncthreads();
    }

    #pragma unroll
    for (int nsub = 0; nsub < 8; nsub++) {
        int d = nsub*8 + tig*2;
        #pragma unroll
        for (int half = 0; half < 2; half++) {
            int p = p00 + wid*16 + g + half*8;
            if (p < NPIX) {
                float2 o; o.x = acc[nsub][2*half]; o.y = acc[nsub][2*half+1];
                *(float2*)(g_E + ((size_t)bb*NPIX + p)*256 + h*DH + d) = o;
            }
        }
    }
}

// ---------------- lin1 GEMM (tf32, 3-term, pre-split W): F = relu(E @ W1t^T + b) ----------------
__global__ __launch_bounds__(256, 2) void lin1_gemm_kernel(const float* __restrict__ b1) {
    extern __shared__ float fsm[];
    int tid = threadIdx.x;
    int lane = tid & 31;
    int wid = tid >> 5;
    int g = lane >> 2, tig = lane & 3;
    size_t m0 = (size_t)blockIdx.x * 128;

    float acc[8][4];
    #pragma unroll
    for (int ni = 0; ni < 8; ni++)
        #pragma unroll
        for (int k = 0; k < 4; k++) acc[ni][k] = 0.f;

    auto loadT = [&](float* b, int kc) {
        #pragma unroll
        for (int j = 0; j < 4; j++) {
            int idx = tid + j*256;
            int r = idx >> 3, q = idx & 7;
            cp16(b + r*SKF + q*4, g_E + (m0 + r)*256 + kc + q*4);
        }
        #pragma unroll
        for (int j = 0; j < 2; j++) {
            int idx = tid + j*256;
            int r = idx >> 3, q = idx & 7;
            cp16(b + FBUF + r*SKF + q*4, g_W1th + r*256 + kc + q*4);
            cp16(b + FBUF + VFBUF + r*SKF + q*4, g_W1tl + r*256 + kc + q*4);
        }
    };

    loadT(fsm, 0);
    CP_COMMIT();
    for (int ch = 0; ch < NCH1; ch++) {
        if (ch + 1 < NCH1) {
            loadT(fsm + ((ch+1)&1)*E3_BUF, (ch+1)*KC);
            CP_COMMIT();
            CP_WAIT1();
        } else {
            CP_WAIT0();
        }
        __syncthreads();
        const float* sE = fsm + (ch&1)*E3_BUF;
        const float* sWh = sE + FBUF;
        const float* sWl = sWh + VFBUF;
        #pragma unroll
        for (int ks = 0; ks < 4; ks++) {
            int ko = ks*8;
            float raw[4], eh[4], el[4];
            const float* ar = sE + (wid*16 + g)*SKF + ko + tig;
            raw[0] = ar[0];
            raw[1] = ar[8*SKF];
            raw[2] = ar[4];
            raw[3] = ar[8*SKF + 4];
            #pragma unroll
            for (int q = 0; q < 4; q++) {
                eh[q] = tf32r(raw[q]);
                el[q] = tf32r(raw[q] - eh[q]);
            }
            #pragma unroll
            for (int nsub = 0; nsub < 8; nsub++) {
                const float* bh = sWh + (nsub*8 + g)*SKF + ko + tig;
                const float* bl = sWl + (nsub*8 + g)*SKF + ko + tig;
                float wh0 = bh[0], wh1 = bh[4];
                float wl0 = bl[0], wl1 = bl[4];
                mma_tf32(acc[nsub], eh, wh0, wh1);
                mma_tf32(acc[nsub], eh, wl0, wl1);
                mma_tf32(acc[nsub], el, wh0, wh1);
            }
        }
        __syncthreads();
    }

    #pragma unroll
    for (int nsub = 0; nsub < 8; nsub++) {
        int d = nsub*8 + tig*2;
        float bb0 = b1[d], bb1 = b1[d+1];
        #pragma unroll
        for (int half = 0; half < 2; half++) {
            size_t m = m0 + wid*16 + g + half*8;
            float2 o;
            o.x = fmaxf(acc[nsub][2*half]   + bb0, 0.f);
            o.y = fmaxf(acc[nsub][2*half+1] + bb1, 0.f);
            *(float2*)(g_F + m*DH + d) = o;
        }
    }
}

// ---------------- LN2 stats ----------------
__global__ void ln2_stats_kernel() {
    int bb = blockIdx.x;
    const float4* base = (const float4*)(g_F + bb*NPIX*DH);
    const int n4 = NPIX*DH/4;
    float s = 0.f, ss = 0.f;
    for (int i = threadIdx.x; i < n4; i += blockDim.x) {
        float4 v = base[i];
        s  += v.x + v.y + v.z + v.w;
        ss += v.x*v.x + v.y*v.y + v.z*v.z + v.w*v.w;
    }
    __shared__ double sh[256], sh2[256];
    sh[threadIdx.x] = (double)s; sh2[threadIdx.x] = (double)ss; __syncthreads();
    for (int o = 128; o; o >>= 1) {
        if (threadIdx.x < o) { sh[threadIdx.x] += sh[threadIdx.x+o]; sh2[threadIdx.x] += sh2[threadIdx.x+o]; }
        __syncthreads();
    }
    if (threadIdx.x == 0) {
        const int n = NPIX*DH;
        double m = sh[0] / (double)n;
        double var = sh2[0] / (double)n - m*m;
        g_mu2[bb] = (float)m;
        g_rv2[bb] = (float)(1.0 / sqrt(var + 1e-5));
    }
}

// ---------------- LN2 apply + max ----------------
__global__ void ln2max_kernel() {
    int bb = blockIdx.x;
    int d = threadIdx.x & 63, pc = threadIdx.x >> 6;
    float mu = g_mu2[bb], rv = g_rv2[bb];
    float m = -1e30f;
    for (int p = pc; p < NPIX; p += 4) {
        float v = (g_F[(bb*NPIX + p)*DH + d] - mu) * rv;
        m = fmaxf(m, v);
    }
    __shared__ float sh[256];
    sh[threadIdx.x] = m; __syncthreads();
    if (pc == 0) {
        m = fmaxf(fmaxf(sh[d], sh[64+d]), fmaxf(sh[128+d], sh[192+d]));
        g_M[bb*DH + d] = m;
    }
}

// ---------------- final lin2 + elu ----------------
__global__ void final_kernel(const float* __restrict__ w, const float* __restrict__ b,
                             float* __restrict__ out) {
    int idx = blockIdx.x * blockDim.x + threadIdx.x;
    if (idx >= NB*10) return;
    int bb = idx / 10, j = idx % 10;
    float acc = b[j];
    #pragma unroll
    for (int d = 0; d < DH; d++) acc += g_M[bb*DH + d] * w[d*10 + j];
    out[idx] = eluf(acc);
}

extern "C" void kernel_launch(void* const* d_in, const int* in_sizes, int n_in,
                              void* d_out, int out_size) {
    const float* x       = (const float*)d_in[0];
    const float* conv1_w = (const float*)d_in[1];
    const float* conv1_b = (const float*)d_in[2];
    const float* conv2_w = (const float*)d_in[3];
    const float* conv2_b = (const float*)d_in[4];
    const float* kp_w    = (const float*)d_in[5];
    const float* kp_b    = (const float*)d_in[6];
    const float* qp_w    = (const float*)d_in[7];
    const float* qp_b    = (const float*)d_in[8];
    const float* vp_w    = (const float*)d_in[9];
    const float* vp_b    = (const float*)d_in[10];
    const float* klin_w  = (const float*)d_in[11];
    const float* klin_b  = (const float*)d_in[12];
    const float* qlin_w  = (const float*)d_in[13];
    const float* qlin_b  = (const float*)d_in[14];
    const float* alin_w  = (const float*)d_in[15];
    const float* alin_b  = (const float*)d_in[16];
    const float* knorm_g = (const float*)d_in[17];
    const float* knorm_b = (const float*)d_in[18];
    const float* qnorm_g = (const float*)d_in[19];
    const float* qnorm_b = (const float*)d_in[20];
    const float* vnorm_g = (const float*)d_in[21];
    const float* vnorm_b = (const float*)d_in[22];
    const float* lin1_w  = (const float*)d_in[23];
    const float* lin1_b  = (const float*)d_in[24];
    const float* lin2_w  = (const float*)d_in[25];
    const float* lin2_b  = (const float*)d_in[26];
    float* out = (float*)d_out;

    cudaFuncSetAttribute(logits_gemm_kernel, cudaFuncAttributeMaxDynamicSharedMemorySize, GEMM_SMEM);
    cudaFuncSetAttribute(gemm_kernel,        cudaFuncAttributeMaxDynamicSharedMemorySize, GEMM_SMEM);
    cudaFuncSetAttribute(e_gemm_kernel,      cudaFuncAttributeMaxDynamicSharedMemorySize, EGEMM_SMEM);
    cudaFuncSetAttribute(lin1_gemm_kernel,   cudaFuncAttributeMaxDynamicSharedMemorySize, E3GEMM_SMEM);
    cudaFuncSetAttribute(proj_gemm_kernel,   cudaFuncAttributeMaxDynamicSharedMemorySize, E3GEMM_SMEM);
    cudaFuncSetAttribute(conv2_gemm_kernel,  cudaFuncAttributeMaxDynamicSharedMemorySize, C2GEMM_SMEM);

    conv1_kernel<<<(NB*16*150*5 + 255)/256, 256>>>(x, conv1_w, conv1_b);
    im2col_kernel<<<(EROWS*64 + 255)/256, 256>>>();
    prep_all_kernel<<<(PREP_TOT + 255)/256, 256>>>(alin_w, qlin_w, klin_w, lin1_w,
                                                   kp_w, qp_w, vp_w, conv2_w);
    conv2_gemm_kernel<<<EROWS/128, 256, C2GEMM_SMEM>>>(conv2_b);
    coords_kernel<<<(EROWS*32 + 255)/256, 256>>>();
    {
        dim3 g(EROWS/128, 12);                     // (298, 12)
        proj_gemm_kernel<<<g, 256, E3GEMM_SMEM>>>(kp_b, qp_b, vp_b);
    }
    {
        dim3 g(NB, 3);
        ln_stats_kernel<<<g, 512>>>();
    }
    {
        dim3 g(PER_B/1024, NB, 3);
        ln_apply_kernel<<<g, 256>>>(knorm_g, knorm_b, qnorm_g, qnorm_b, vnorm_g, vnorm_b);
    }
    {
        dim3 g(KPAD/128, MROWS/128);               // (5, 1192)
        logits_gemm_kernel<<<g, 128, GEMM_SMEM>>>(qlin_b, klin_b);
    }
    {
        dim3 g(KPAD/128, MROWS/128);               // (5, 1192)
        gemm_kernel<<<g, 128, GEMM_SMEM>>>(alin_b);
    }
    vtrans_kernel<<<NB*HEADS, 256>>>();
    softmax_kernel<<<MROWS/8, 256>>>();
    {
        dim3 g(5, NB*HEADS);                       // (5, 256)
        e_gemm_kernel<<<g, 256, EGEMM_SMEM>>>();
    }
    lin1_gemm_kernel<<<EROWS/128, 256, E3GEMM_SMEM>>>(lin1_b);
    ln2_stats_kernel<<<NB, 256>>>();
    ln2max_kernel<<<NB, 256>>>();
    final_kernel<<<3, 256>>>(lin2_w, lin2_b, out);
}

// round 14
// speedup vs baseline: 1.3535x; 1.0447x over previous
#include <cuda_runtime.h>
#include <cuda_bf16.h>
#include <math.h>
#include <stdint.h>

#define NB 64
#define NPIX 596
#define HEADS 4
#define DH 64
#define PER_B (HEADS*NPIX*DH)   // 152576
#define MROWS (NB*HEADS*NPIX)   // 152576
#define EROWS (NB*NPIX)         // 38144
#define KPAD 640

// ---- tf32 gemm common ----
#define KC 32
#define NCH (KPAD/KC)           // 20
#define NCHL (128/KC)           // 4
#define NCH1 (256/KC)           // 8
#define NCHP (64/KC)            // 2
#define SKF 36
#define FBUF (128*SKF)
#define VFBUF (64*SKF)
#define G_BUF (2*FBUF)
#define GEMM_SMEM (2*G_BUF*4)                   // 73728
#define E_BUF (FBUF + VFBUF)
#define EGEMM_SMEM (2*E_BUF*4)                  // 55296
#define E3_BUF (FBUF + 2*VFBUF)
#define E3GEMM_SMEM (2*E3_BUF*4)                // 73728
#define C2_BUF (FBUF + 2*32*SKF)
#define C2GEMM_SMEM (2*C2_BUF*4)                // 55296

// ---------------- scratch ----------------
__device__ float g_conv1[NB*16*150*5];
__device__ float g_col[(size_t)EROWS*64];
__device__ float g_feats[(size_t)EROWS*64];
__device__ float g_K[NB*HEADS*NPIX*DH];
__device__ float g_Q[NB*HEADS*NPIX*DH];
__device__ float g_V[NB*HEADS*NPIX*DH];
__device__ float g_Wkqvh[768*64], g_Wkqvl[768*64];
__device__ float g_Wc2h[32*64],  g_Wc2l[32*64];
__device__ float g_W1th[64*256], g_W1tl[64*256];
__device__ float g_mu[3*NB], g_rv[3*NB];
__device__ float g_QKf[(size_t)MROWS*128];
__device__ float g_Wqkf[(size_t)KPAD*128];
__device__ float g_A[(size_t)MROWS*KPAD];
__device__ float g_Wf[(size_t)KPAD*KPAD];
__device__ float g_Vt[(size_t)NB*HEADS*DH*KPAD];
__device__ float g_S[(size_t)MROWS*NPIX];
__device__ float g_P[(size_t)MROWS*KPAD];
__device__ float g_E[(size_t)EROWS*256];
__device__ float g_F[EROWS*DH];
__device__ float g_M[NB*DH];

__device__ __forceinline__ float eluf(float x) {
    return x > 0.f ? x : (__expf(x) - 1.f);
}
__device__ __forceinline__ float tf32r(float x) {
    uint32_t u;
    asm("cvt.rna.tf32.f32 %0, %1;" : "=r"(u) : "f"(x));
    return __uint_as_float(u);
}

// ---- mma.sync tf32 ----
__device__ __forceinline__ void mma_tf32(float* c, const float* a, float b0, float b1) {
    asm volatile(
        "mma.sync.aligned.m16n8k8.row.col.f32.tf32.tf32.f32 "
        "{%0,%1,%2,%3}, {%4,%5,%6,%7}, {%8,%9}, {%0,%1,%2,%3};"
        : "+f"(c[0]), "+f"(c[1]), "+f"(c[2]), "+f"(c[3])
        : "r"(__float_as_uint(a[0])), "r"(__float_as_uint(a[1])),
          "r"(__float_as_uint(a[2])), "r"(__float_as_uint(a[3])),
          "r"(__float_as_uint(b0)), "r"(__float_as_uint(b1)));
}
// ---- cp.async ----
__device__ __forceinline__ void cp16(void* smem, const void* gmem) {
    uint32_t s = (uint32_t)__cvta_generic_to_shared(smem);
    asm volatile("cp.async.cg.shared.global [%0], [%1], 16;" :: "r"(s), "l"(gmem));
}
#define CP_COMMIT() asm volatile("cp.async.commit_group;" ::: "memory")
#define CP_WAIT1()  asm volatile("cp.async.wait_group 1;" ::: "memory")
#define CP_WAIT0()  asm volatile("cp.async.wait_group 0;" ::: "memory")

// ---------------- conv1 + relu ----------------
__global__ void conv1_kernel(const float* __restrict__ x,
                             const float* __restrict__ w,
                             const float* __restrict__ b) {
    int idx = blockIdx.x * blockDim.x + threadIdx.x;
    if (idx >= NB*16*150*5) return;
    int ow = idx % 5;
    int oh = (idx / 5) % 150;
    int co = (idx / (5*150)) % 16;
    int bb = idx / (5*150*16);
    float acc = b[co];
    #pragma unroll
    for (int ci = 0; ci < 4; ci++)
        #pragma unroll
        for (int kh = 0; kh < 2; kh++)
            #pragma unroll
            for (int kw = 0; kw < 2; kw++)
                acc += x[((bb*4+ci)*151 + oh+kh)*6 + ow+kw] *
                       w[((co*4+ci)*2 + kh)*2 + kw];
    g_conv1[idx] = fmaxf(acc, 0.f);
}

// ---------------- im2col + coords (merged) ----------------
__global__ void im2col_coords_kernel() {
    int idx = blockIdx.x * blockDim.x + threadIdx.x;
    if (idx < EROWS*64) {
        int c = idx & 63;
        int bp = idx >> 6;
        int p = bp % NPIX, bb = bp / NPIX;
        int oh = p / 4, ow = p % 4;
        int ci = c >> 2, kh = (c >> 1) & 1, kw = c & 1;
        g_col[idx] = g_conv1[((bb*16+ci)*150 + oh+kh)*5 + ow+kw];
        return;
    }
    idx -= EROWS*64;
    if (idx < EROWS*32) {
        int c = 32 + (idx & 31);
        int bp = idx >> 5;
        int p = bp % NPIX;
        float v = 0.f;
        if (c == 32) v = (float)(p % 4) / 4.f;
        else if (c == 33) v = (float)(p / 4) / 149.f;
        g_feats[(size_t)bp*64 + c] = v;
    }
}

// ---------------- conv2 GEMM (tf32 3-term, pre-split W): feats[:, :32] ----------------
__global__ __launch_bounds__(256, 2) void conv2_gemm_kernel(const float* __restrict__ b2) {
    extern __shared__ float fsm[];
    int tid = threadIdx.x;
    int lane = tid & 31;
    int wid = tid >> 5;
    int g = lane >> 2, tig = lane & 3;
    size_t m0 = (size_t)blockIdx.x * 128;

    float acc[4][4];
    #pragma unroll
    for (int ni = 0; ni < 4; ni++)
        #pragma unroll
        for (int k = 0; k < 4; k++) acc[ni][k] = 0.f;

    auto loadT = [&](float* b, int kc) {
        #pragma unroll
        for (int j = 0; j < 4; j++) {
            int idx = tid + j*256;
            int r = idx >> 3, q = idx & 7;
            cp16(b + r*SKF + q*4, g_col + (m0 + r)*64 + kc + q*4);
        }
        {
            int r = tid >> 3, q = tid & 7;
            cp16(b + FBUF + r*SKF + q*4, g_Wc2h + r*64 + kc + q*4);
            cp16(b + FBUF + 32*SKF + r*SKF + q*4, g_Wc2l + r*64 + kc + q*4);
        }
    };

    loadT(fsm, 0);
    CP_COMMIT();
    for (int ch = 0; ch < NCHP; ch++) {
        if (ch + 1 < NCHP) {
            loadT(fsm + ((ch+1)&1)*C2_BUF, (ch+1)*KC);
            CP_COMMIT();
            CP_WAIT1();
        } else {
            CP_WAIT0();
        }
        __syncthreads();
        const float* sE = fsm + (ch&1)*C2_BUF;
        const float* sWh = sE + FBUF;
        const float* sWl = sWh + 32*SKF;
        #pragma unroll
        for (int ks = 0; ks < 4; ks++) {
            int ko = ks*8;
            float raw[4], eh[4], el[4];
            const float* ar = sE + (wid*16 + g)*SKF + ko + tig;
            raw[0] = ar[0];
            raw[1] = ar[8*SKF];
            raw[2] = ar[4];
            raw[3] = ar[8*SKF + 4];
            #pragma unroll
            for (int q = 0; q < 4; q++) {
                eh[q] = tf32r(raw[q]);
                el[q] = tf32r(raw[q] - eh[q]);
            }
            #pragma unroll
            for (int nsub = 0; nsub < 4; nsub++) {
                const float* bh = sWh + (nsub*8 + g)*SKF + ko + tig;
                const float* bl = sWl + (nsub*8 + g)*SKF + ko + tig;
                float wh0 = bh[0], wh1 = bh[4];
                float wl0 = bl[0], wl1 = bl[4];
                mma_tf32(acc[nsub], eh, wh0, wh1);
                mma_tf32(acc[nsub], eh, wl0, wl1);
                mma_tf32(acc[nsub], el, wh0, wh1);
            }
        }
        __syncthreads();
    }

    #pragma unroll
    for (int nsub = 0; nsub < 4; nsub++) {
        int n = nsub*8 + tig*2;
        float b0 = b2[n], b1 = b2[n+1];
        #pragma unroll
        for (int half = 0; half < 2; half++) {
            size_t m = m0 + wid*16 + g + half*8;
            float2 o;
            o.x = fmaxf(acc[nsub][2*half]   + b0, 0.f);
            o.y = fmaxf(acc[nsub][2*half+1] + b1, 0.f);
            *(float2*)(g_feats + m*64 + n) = o;
        }
    }
}

// ---------------- proj GEMM (tf32 3-term, pre-split W): [K|Q|V] ----------------
__global__ __launch_bounds__(256, 2) void proj_gemm_kernel(
    const float* __restrict__ kb, const float* __restrict__ qb,
    const float* __restrict__ vb) {
    extern __shared__ float fsm[];
    int tid = threadIdx.x;
    int lane = tid & 31;
    int wid = tid >> 5;
    int g = lane >> 2, tig = lane & 3;
    size_t m0 = (size_t)blockIdx.x * 128;
    int n0 = blockIdx.y * 64;

    float acc[8][4];
    #pragma unroll
    for (int ni = 0; ni < 8; ni++)
        #pragma unroll
        for (int k = 0; k < 4; k++) acc[ni][k] = 0.f;

    auto loadT = [&](float* b, int kc) {
        #pragma unroll
        for (int j = 0; j < 4; j++) {
            int idx = tid + j*256;
            int r = idx >> 3, q = idx & 7;
            cp16(b + r*SKF + q*4, g_feats + (m0 + r)*64 + kc + q*4);
        }
        #pragma unroll
        for (int j = 0; j < 2; j++) {
            int idx = tid + j*256;
            int r = idx >> 3, q = idx & 7;
            cp16(b + FBUF + r*SKF + q*4, g_Wkqvh + (n0 + r)*64 + kc + q*4);
            cp16(b + FBUF + VFBUF + r*SKF + q*4, g_Wkqvl + (n0 + r)*64 + kc + q*4);
        }
    };

    loadT(fsm, 0);
    CP_COMMIT();
    for (int ch = 0; ch < NCHP; ch++) {
        if (ch + 1 < NCHP) {
            loadT(fsm + ((ch+1)&1)*E3_BUF, (ch+1)*KC);
            CP_COMMIT();
            CP_WAIT1();
        } else {
            CP_WAIT0();
        }
        __syncthreads();
        const float* sE = fsm + (ch&1)*E3_BUF;
        const float* sWh = sE + FBUF;
        const float* sWl = sWh + VFBUF;
        #pragma unroll
        for (int ks = 0; ks < 4; ks++) {
            int ko = ks*8;
            float raw[4], eh[4], el[4];
            const float* ar = sE + (wid*16 + g)*SKF + ko + tig;
            raw[0] = ar[0];
            raw[1] = ar[8*SKF];
            raw[2] = ar[4];
            raw[3] = ar[8*SKF + 4];
            #pragma unroll
            for (int q = 0; q < 4; q++) {
                eh[q] = tf32r(raw[q]);
                el[q] = tf32r(raw[q] - eh[q]);
            }
            #pragma unroll
            for (int nsub = 0; nsub < 8; nsub++) {
                const float* bh = sWh + (nsub*8 + g)*SKF + ko + tig;
                const float* bl = sWl + (nsub*8 + g)*SKF + ko + tig;
                float wh0 = bh[0], wh1 = bh[4];
                float wl0 = bl[0], wl1 = bl[4];
                mma_tf32(acc[nsub], eh, wh0, wh1);
                mma_tf32(acc[nsub], eh, wl0, wl1);
                mma_tf32(acc[nsub], el, wh0, wh1);
            }
        }
        __syncthreads();
    }

    int mloc[2], bbv[2], pv[2];
    #pragma unroll
    for (int half = 0; half < 2; half++) {
        mloc[half] = (int)(m0 + wid*16 + g + half*8);
        bbv[half] = mloc[half] / NPIX;
        pv[half]  = mloc[half] % NPIX;
    }
    #pragma unroll
    for (int nsub = 0; nsub < 8; nsub++) {
        int n = n0 + nsub*8 + tig*2;
        int t = n >> 8;
        int hd = n & 255;
        int h = hd >> 6, d = hd & 63;
        const float* B = t == 0 ? kb : t == 1 ? qb : vb;
        float* O = t == 0 ? g_K : t == 1 ? g_Q : g_V;
        float b0 = B[hd], b1 = B[hd+1];
        #pragma unroll
        for (int half = 0; half < 2; half++) {
            float2 o;
            o.x = acc[nsub][2*half]   + b0;
            o.y = acc[nsub][2*half+1] + b1;
            *(float2*)(O + ((size_t)(bbv[half]*HEADS + h)*NPIX + pv[half])*DH + d) = o;
        }
    }
}

// ---------------- LN stats (512 thr, float4) ----------------
__global__ __launch_bounds__(512) void ln_stats_kernel() {
    int bb = blockIdx.x, t = blockIdx.y;
    const float4* base = (const float4*)((t==0 ? g_K : t==1 ? g_Q : g_V) + bb*PER_B);
    const int n4 = PER_B/4;
    float s = 0.f, ss = 0.f;
    for (int i = threadIdx.x; i < n4; i += 512) {
        float4 v = base[i];
        s  += v.x + v.y + v.z + v.w;
        ss += v.x*v.x + v.y*v.y + v.z*v.z + v.w*v.w;
    }
    __shared__ double sh[512], sh2[512];
    sh[threadIdx.x] = (double)s; sh2[threadIdx.x] = (double)ss; __syncthreads();
    for (int o = 256; o; o >>= 1) {
        if (threadIdx.x < o) { sh[threadIdx.x] += sh[threadIdx.x+o]; sh2[threadIdx.x] += sh2[threadIdx.x+o]; }
        __syncthreads();
    }
    if (threadIdx.x == 0) {
        double m = sh[0] / (double)PER_B;
        double var = sh2[0] / (double)PER_B - m*m;
        g_mu[t*NB+bb] = (float)m;
        g_rv[t*NB+bb] = (float)(1.0 / sqrt(var + 1e-5));
    }
}

// ---------------- LN apply: Q,K -> tf32-rounded QK concat; V -> fp32 ----------------
__global__ void ln_apply_kernel(const float* __restrict__ kg, const float* __restrict__ kb,
                                const float* __restrict__ qg, const float* __restrict__ qb,
                                const float* __restrict__ vg, const float* __restrict__ vb) {
    int t = blockIdx.z;
    int bb = blockIdx.y;
    const float* base = (t==0 ? g_K : t==1 ? g_Q : g_V) + bb*PER_B;
    const float* g = t==0 ? kg : t==1 ? qg : vg;
    const float* be = t==0 ? kb : t==1 ? qb : vb;
    int off = (blockIdx.x*256 + threadIdx.x)*4;
    float mu = g_mu[t*NB+bb], rv = g_rv[t*NB+bb];
    float4 v  = *(const float4*)(base + off);
    float4 gg = *(const float4*)(g + off);
    float4 bv = *(const float4*)(be + off);
    float4 r;
    r.x = (v.x - mu)*rv*gg.x + bv.x;
    r.y = (v.y - mu)*rv*gg.y + bv.y;
    r.z = (v.z - mu)*rv*gg.z + bv.z;
    r.w = (v.w - mu)*rv*gg.w + bv.w;
    if (t == 2) {
        *(float4*)(g_V + bb*PER_B + off) = r;
    } else {
        int d = off & 63;
        int hp = off >> 6;
        size_t row = (size_t)bb*HEADS*NPIX + hp;
        int col = d + (t == 0 ? 64 : 0);
        float4 o;
        o.x = tf32r(r.x); o.y = tf32r(r.y); o.z = tf32r(r.z); o.w = tf32r(r.w);
        *(float4*)(g_QKf + row*128 + col) = o;
    }
}

// ---------------- V transpose (tf32-rounded): Vt[bh][d][p_pad] ----------------
__global__ void vtrans_kernel() {
    __shared__ float tile[32][65];
    int bhid = blockIdx.x;
    const float* Vb = g_V + (size_t)bhid*NPIX*DH;
    int t = threadIdx.x;
    for (int pt = 0; pt < 20; pt++) {
        int p0 = pt*32;
        for (int i = t; i < 32*64; i += 256) {
            int r = i >> 6, c = i & 63;
            tile[r][c] = (p0 + r < NPIX) ? Vb[(p0 + r)*DH + c] : 0.f;
        }
        __syncthreads();
        for (int i = t; i < 64*32; i += 256) {
            int d = i >> 5, pp = i & 31;
            g_Vt[((size_t)bhid*DH + d)*KPAD + p0 + pp] = tf32r(tile[pp][d]);
        }
        __syncthreads();
    }
}

// ---------------- merged weight prep ----------------
__global__ void prep_all_kernel(const float* __restrict__ alw,
                                const float* __restrict__ qlw,
                                const float* __restrict__ klw,
                                const float* __restrict__ w1,
                                const float* __restrict__ kpw,
                                const float* __restrict__ qpw,
                                const float* __restrict__ vpw,
                                const float* __restrict__ c2w) {
    int idx = blockIdx.x*256 + threadIdx.x;
    if (idx < KPAD*KPAD) {
        int k = idx / KPAD, n = idx % KPAD;
        float v = (k < NPIX && n < NPIX) ? alw[k*NPIX + n] : 0.f;
        g_Wf[(size_t)n*KPAD + k] = tf32r(v);
        return;
    }
    idx -= KPAD*KPAD;
    if (idx < KPAD*128) {
        int n = idx >> 7, k = idx & 127;
        float v = 0.f;
        if (n < NPIX) v = (k < 64) ? qlw[k*NPIX + n] : klw[(k-64)*NPIX + n];
        g_Wqkf[(size_t)n*128 + k] = tf32r(v);
        return;
    }
    idx -= KPAD*128;
    if (idx < 64*256) {
        int d = idx >> 8, c = idx & 255;
        float v = w1[c*64 + d];
        float h = tf32r(v);
        g_W1th[d*256 + c] = h;
        g_W1tl[d*256 + c] = tf32r(v - h);
        return;
    }
    idx -= 64*256;
    if (idx < 768*64) {
        int n = idx >> 6, c = idx & 63;
        int t = n >> 8, hd = n & 255;
        const float* W = t == 0 ? kpw : t == 1 ? qpw : vpw;
        float v = (c < 34) ? W[c*256 + hd] : 0.f;
        float h = tf32r(v);
        g_Wkqvh[n*64 + c] = h;
        g_Wkqvl[n*64 + c] = tf32r(v - h);
        return;
    }
    idx -= 768*64;
    if (idx < 32*64) {
        int n = idx >> 6, c = idx & 63;
        int ci = c >> 2, kh = (c >> 1) & 1, kw = c & 1;
        float v = c2w[((n*16+ci)*2 + kh)*2 + kw];
        float h = tf32r(v);
        g_Wc2h[n*64 + c] = h;
        g_Wc2l[n*64 + c] = tf32r(v - h);
    }
}
#define PREP_TOT (KPAD*KPAD + KPAD*128 + 64*256 + 768*64 + 32*64)

// ---------------- pipelined cp.async tile loaders (fp32, 128 thr) ----------------
__device__ __forceinline__ void cp_ftile_t128(float* dst, const float* g,
                                              size_t row0, int kc, int tid, int gstride) {
    #pragma unroll
    for (int j = 0; j < 8; j++) {
        int idx = tid + j*128;
        int r = idx >> 3, q = idx & 7;
        cp16(dst + r*SKF + q*4, g + (row0 + r)*(size_t)gstride + kc + q*4);
    }
}

// ---------------- tf32 GEMM inner step: 4 warps, warp tile 64x64 ----------------
__device__ __forceinline__ void tf32_step4(const float* sA, const float* sW, int ko,
                                           int wm, int wn, int g, int tig,
                                           float acc[4][8][4]) {
    float af[4][4];
    #pragma unroll
    for (int mi = 0; mi < 4; mi++) {
        const float* ar = sA + (wm*64 + mi*16 + g)*SKF + ko + tig;
        af[mi][0] = ar[0];
        af[mi][1] = ar[8*SKF];
        af[mi][2] = ar[4];
        af[mi][3] = ar[8*SKF + 4];
    }
    #pragma unroll
    for (int nsub = 0; nsub < 8; nsub++) {
        const float* br = sW + (wn*64 + nsub*8 + g)*SKF + ko + tig;
        float b0 = br[0], b1 = br[4];
        #pragma unroll
        for (int mi = 0; mi < 4; mi++)
            mma_tf32(acc[mi][nsub], af[mi], b0, b1);
    }
}

// ---------------- logits GEMM (tf32, 128 thr, occ 3): A = elu(QK @ Wqk^T + bias) ----------------
__global__ __launch_bounds__(128, 3) void logits_gemm_kernel(
    const float* __restrict__ qlb, const float* __restrict__ klb) {
    extern __shared__ float fsm[];
    int tid = threadIdx.x;
    int lane = tid & 31;
    int wid = tid >> 5;
    int wm = wid & 1, wn = wid >> 1;
    int g = lane >> 2, tig = lane & 3;
    int n0 = blockIdx.x * 128;
    size_t m0 = (size_t)blockIdx.y * 128;

    float acc[4][8][4];
    #pragma unroll
    for (int mi = 0; mi < 4; mi++)
        #pragma unroll
        for (int ni = 0; ni < 8; ni++)
            #pragma unroll
            for (int k = 0; k < 4; k++) acc[mi][ni][k] = 0.f;

    {
        float* b = fsm;
        cp_ftile_t128(b,        g_QKf,  m0, 0, tid, 128);
        cp_ftile_t128(b + FBUF, g_Wqkf, n0, 0, tid, 128);
        CP_COMMIT();
    }
    for (int ch = 0; ch < NCHL; ch++) {
        if (ch + 1 < NCHL) {
            float* b = fsm + ((ch+1)&1)*G_BUF;
            int kc = (ch+1)*KC;
            cp_ftile_t128(b,        g_QKf,  m0, kc, tid, 128);
            cp_ftile_t128(b + FBUF, g_Wqkf, n0, kc, tid, 128);
            CP_COMMIT();
            CP_WAIT1();
        } else {
            CP_WAIT0();
        }
        __syncthreads();
        const float* sA = fsm + (ch&1)*G_BUF;
        const float* sW = sA + FBUF;
        #pragma unroll
        for (int ks = 0; ks < 4; ks++)
            tf32_step4(sA, sW, ks*8, wm, wn, g, tig, acc);
        __syncthreads();
    }

    #pragma unroll
    for (int mi = 0; mi < 4; mi++) {
        #pragma unroll
        for (int nsub = 0; nsub < 8; nsub++) {
            int n = n0 + wn*64 + nsub*8 + tig*2;
            float b0 = (n < NPIX)   ? qlb[n] + klb[n]     : 0.f;
            float b1 = (n+1 < NPIX) ? qlb[n+1] + klb[n+1] : 0.f;
            #pragma unroll
            for (int half = 0; half < 2; half++) {
                size_t m = m0 + wm*64 + mi*16 + g + half*8;
                float2 o;
                o.x = tf32r(eluf(acc[mi][nsub][2*half]   + b0));
                o.y = tf32r(eluf(acc[mi][nsub][2*half+1] + b1));
                *(float2*)(g_A + m*KPAD + n) = o;
            }
        }
    }
}

// ---------------- main GEMM (tf32, 128 thr, occ 3): S = A @ W^T + alb ----------------
__global__ __launch_bounds__(128, 3) void gemm_kernel(const float* __restrict__ alb) {
    extern __shared__ float fsm[];
    int tid = threadIdx.x;
    int lane = tid & 31;
    int wid = tid >> 5;
    int wm = wid & 1, wn = wid >> 1;
    int g = lane >> 2, tig = lane & 3;
    int n0 = blockIdx.x * 128;
    size_t m0 = (size_t)blockIdx.y * 128;

    float acc[4][8][4];
    #pragma unroll
    for (int mi = 0; mi < 4; mi++)
        #pragma unroll
        for (int ni = 0; ni < 8; ni++)
            #pragma unroll
            for (int k = 0; k < 4; k++) acc[mi][ni][k] = 0.f;

    {
        float* b = fsm;
        cp_ftile_t128(b,        g_A,  m0, 0, tid, KPAD);
        cp_ftile_t128(b + FBUF, g_Wf, n0, 0, tid, KPAD);
        CP_COMMIT();
    }
    for (int ch = 0; ch < NCH; ch++) {
        if (ch + 1 < NCH) {
            float* b = fsm + ((ch+1)&1)*G_BUF;
            int kc = (ch+1)*KC;
            cp_ftile_t128(b,        g_A,  m0, kc, tid, KPAD);
            cp_ftile_t128(b + FBUF, g_Wf, n0, kc, tid, KPAD);
            CP_COMMIT();
            CP_WAIT1();
        } else {
            CP_WAIT0();
        }
        __syncthreads();
        const float* sA = fsm + (ch&1)*G_BUF;
        const float* sW = sA + FBUF;
        #pragma unroll
        for (int ks = 0; ks < 4; ks++)
            tf32_step4(sA, sW, ks*8, wm, wn, g, tig, acc);
        __syncthreads();
    }

    #pragma unroll
    for (int mi = 0; mi < 4; mi++) {
        #pragma unroll
        for (int nsub = 0; nsub < 8; nsub++) {
            int n = n0 + wn*64 + nsub*8 + tig*2;
            #pragma unroll
            for (int half = 0; half < 2; half++) {
                size_t m = m0 + wm*64 + mi*16 + g + half*8;
                if (n + 1 < NPIX) {
                    float2 o;
                    o.x = acc[mi][nsub][2*half]   + alb[n];
                    o.y = acc[mi][nsub][2*half+1] + alb[n+1];
                    *(float2*)(g_S + m*NPIX + n) = o;
                } else if (n < NPIX) {
                    g_S[m*NPIX + n] = acc[mi][nsub][2*half] + alb[n];
                }
            }
        }
    }
}

// ---------------- softmax (float4): g_S -> g_P (tf32-rounded, zero-padded) ----------------
__global__ __launch_bounds__(256) void softmax_kernel() {
    size_t row = (size_t)blockIdx.x*8 + (threadIdx.x >> 5);
    int lane = threadIdx.x & 31;
    const float4* S4 = (const float4*)(g_S + row*NPIX);
    float* P = g_P + row*KPAD;
    float4 v[5];
    float m = -1e30f;
    #pragma unroll
    for (int i = 0; i < 5; i++) {
        int j = lane + 32*i;
        if (j < 149) {
            v[i] = S4[j];
            m = fmaxf(m, fmaxf(fmaxf(v[i].x, v[i].y), fmaxf(v[i].z, v[i].w)));
        } else {
            v[i].x = v[i].y = v[i].z = v[i].w = -1e30f;
        }
    }
    #pragma unroll
    for (int o = 16; o; o >>= 1) m = fmaxf(m, __shfl_xor_sync(0xffffffffu, m, o));
    float s = 0.f;
    #pragma unroll
    for (int i = 0; i < 5; i++) {
        v[i].x = __expf(v[i].x - m); v[i].y = __expf(v[i].y - m);
        v[i].z = __expf(v[i].z - m); v[i].w = __expf(v[i].w - m);
        if (lane + 32*i < 149) s += v[i].x + v[i].y + v[i].z + v[i].w;
    }
    #pragma unroll
    for (int o = 16; o; o >>= 1) s += __shfl_xor_sync(0xffffffffu, s, o);
    float inv = 1.f / s;
    #pragma unroll
    for (int i = 0; i < 5; i++) {
        int j = lane + 32*i;
        if (j < 149) {
            float4 o;
            o.x = tf32r(v[i].x*inv); o.y = tf32r(v[i].y*inv);
            o.z = tf32r(v[i].z*inv); o.w = tf32r(v[i].w*inv);
            *(float4*)(P + 4*j) = o;
        }
    }
    if (lane < 11) {
        float4 z; z.x = z.y = z.z = z.w = 0.f;
        *(float4*)(P + 596 + 4*lane) = z;
    }
}

// ---------------- E GEMM (tf32): E = P @ Vt^T per bh (fp32 out) ----------------
__global__ __launch_bounds__(256, 2) void e_gemm_kernel() {
    extern __shared__ float fsm[];
    int tid = threadIdx.x;
    int lane = tid & 31;
    int wid = tid >> 5;
    int g = lane >> 2, tig = lane & 3;
    int mt = blockIdx.x;
    int bhid = blockIdx.y;
    int p00 = mt * 128;
    int bb = bhid >> 2, h = bhid & 3;

    float acc[8][4];
    #pragma unroll
    for (int ni = 0; ni < 8; ni++)
        #pragma unroll
        for (int k = 0; k < 4; k++) acc[ni][k] = 0.f;

    auto loadT = [&](float* b, int kc) {
        #pragma unroll
        for (int j = 0; j < 4; j++) {
            int idx = tid + j*256;
            int r = idx >> 3, q = idx & 7;
            int p = p00 + r; if (p > NPIX-1) p = NPIX-1;
            cp16(b + r*SKF + q*4, g_P + ((size_t)bhid*NPIX + p)*KPAD + kc + q*4);
        }
        #pragma unroll
        for (int j = 0; j < 2; j++) {
            int idx = tid + j*256;
            int r = idx >> 3, q = idx & 7;
            cp16(b + FBUF + r*SKF + q*4, g_Vt + ((size_t)bhid*DH + r)*KPAD + kc + q*4);
        }
    };

    loadT(fsm, 0);
    CP_COMMIT();
    for (int ch = 0; ch < NCH; ch++) {
        if (ch + 1 < NCH) {
            loadT(fsm + ((ch+1)&1)*E_BUF, (ch+1)*KC);
            CP_COMMIT();
            CP_WAIT1();
        } else {
            CP_WAIT0();
        }
        __syncthreads();
        const float* sP = fsm + (ch&1)*E_BUF;
        const float* sV = sP + FBUF;
        #pragma unroll
        for (int ks = 0; ks < 4; ks++) {
            int ko = ks*8;
            float af[4];
            const float* ar = sP + (wid*16 + g)*SKF + ko + tig;
            af[0] = ar[0];
            af[1] = ar[8*SKF];
            af[2] = ar[4];
            af[3] = ar[8*SKF + 4];
            #pragma unroll
            for (int nsub = 0; nsub < 8; nsub++) {
                const float* br = sV + (nsub*8 + g)*SKF + ko + tig;
                mma_tf32(acc[nsub], af, br[0], br[4]);
            }
        }
        __syncthreads();
    }

    #pragma unroll
    for (int nsub = 0; nsub < 8; nsub++) {
        int d = nsub*8 + tig*2;
        #pragma unroll
        for (int half = 0; half < 2; half++) {
            int p = p00 + wid*16 + g + half*8;
            if (p < NPIX) {
                float2 o; o.x = acc[nsub][2*half]; o.y = acc[nsub][2*half+1];
                *(float2*)(g_E + ((size_t)bb*NPIX + p)*256 + h*DH + d) = o;
            }
        }
    }
}

// ---------------- lin1 GEMM (tf32, 3-term, pre-split W): F = relu(E @ W1t^T + b) ----------------
__global__ __launch_bounds__(256, 2) void lin1_gemm_kernel(const float* __restrict__ b1) {
    extern __shared__ float fsm[];
    int tid = threadIdx.x;
    int lane = tid & 31;
    int wid = tid >> 5;
    int g = lane >> 2, tig = lane & 3;
    size_t m0 = (size_t)blockIdx.x * 128;

    float acc[8][4];
    #pragma unroll
    for (int ni = 0; ni < 8; ni++)
        #pragma unroll
        for (int k = 0; k < 4; k++) acc[ni][k] = 0.f;

    auto loadT = [&](float* b, int kc) {
        #pragma unroll
        for (int j = 0; j < 4; j++) {
            int idx = tid + j*256;
            int r = idx >> 3, q = idx & 7;
            cp16(b + r*SKF + q*4, g_E + (m0 + r)*256 + kc + q*4);
        }
        #pragma unroll
        for (int j = 0; j < 2; j++) {
            int idx = tid + j*256;
            int r = idx >> 3, q = idx & 7;
            cp16(b + FBUF + r*SKF + q*4, g_W1th + r*256 + kc + q*4);
            cp16(b + FBUF + VFBUF + r*SKF + q*4, g_W1tl + r*256 + kc + q*4);
        }
    };

    loadT(fsm, 0);
    CP_COMMIT();
    for (int ch = 0; ch < NCH1; ch++) {
        if (ch + 1 < NCH1) {
            loadT(fsm + ((ch+1)&1)*E3_BUF, (ch+1)*KC);
            CP_COMMIT();
            CP_WAIT1();
        } else {
            CP_WAIT0();
        }
        __syncthreads();
        const float* sE = fsm + (ch&1)*E3_BUF;
        const float* sWh = sE + FBUF;
        const float* sWl = sWh + VFBUF;
        #pragma unroll
        for (int ks = 0; ks < 4; ks++) {
            int ko = ks*8;
            float raw[4], eh[4], el[4];
            const float* ar = sE + (wid*16 + g)*SKF + ko + tig;
            raw[0] = ar[0];
            raw[1] = ar[8*SKF];
            raw[2] = ar[4];
            raw[3] = ar[8*SKF + 4];
            #pragma unroll
            for (int q = 0; q < 4; q++) {
                eh[q] = tf32r(raw[q]);
                el[q] = tf32r(raw[q] - eh[q]);
            }
            #pragma unroll
            for (int nsub = 0; nsub < 8; nsub++) {
                const float* bh = sWh + (nsub*8 + g)*SKF + ko + tig;
                const float* bl = sWl + (nsub*8 + g)*SKF + ko + tig;
                float wh0 = bh[0], wh1 = bh[4];
                float wl0 = bl[0], wl1 = bl[4];
                mma_tf32(acc[nsub], eh, wh0, wh1);
                mma_tf32(acc[nsub], eh, wl0, wl1);
                mma_tf32(acc[nsub], el, wh0, wh1);
            }
        }
        __syncthreads();
    }

    #pragma unroll
    for (int nsub = 0; nsub < 8; nsub++) {
        int d = nsub*8 + tig*2;
        float bb0 = b1[d], bb1 = b1[d+1];
        #pragma unroll
        for (int half = 0; half < 2; half++) {
            size_t m = m0 + wid*16 + g + half*8;
            float2 o;
            o.x = fmaxf(acc[nsub][2*half]   + bb0, 0.f);
            o.y = fmaxf(acc[nsub][2*half+1] + bb1, 0.f);
            *(float2*)(g_F + m*DH + d) = o;
        }
    }
}

// ---------------- LN2 (merged stats + apply + max), one block per batch ----------------
__global__ __launch_bounds__(256) void ln2_kernel() {
    int bb = blockIdx.x;
    const float4* base = (const float4*)(g_F + bb*NPIX*DH);
    const int n4 = NPIX*DH/4;
    float s = 0.f, ss = 0.f;
    for (int i = threadIdx.x; i < n4; i += 256) {
        float4 v = base[i];
        s  += v.x + v.y + v.z + v.w;
        ss += v.x*v.x + v.y*v.y + v.z*v.z + v.w*v.w;
    }
    __shared__ double sh[256], sh2[256];
    __shared__ float smu, srv;
    sh[threadIdx.x] = (double)s; sh2[threadIdx.x] = (double)ss; __syncthreads();
    for (int o = 128; o; o >>= 1) {
        if (threadIdx.x < o) { sh[threadIdx.x] += sh[threadIdx.x+o]; sh2[threadIdx.x] += sh2[threadIdx.x+o]; }
        __syncthreads();
    }
    if (threadIdx.x == 0) {
        const int n = NPIX*DH;
        double m = sh[0] / (double)n;
        double var = sh2[0] / (double)n - m*m;
        smu = (float)m;
        srv = (float)(1.0 / sqrt(var + 1e-5));
    }
    __syncthreads();
    float mu = smu, rv = srv;
    int d = threadIdx.x & 63, pc = threadIdx.x >> 6;
    float m = -1e30f;
    for (int p = pc; p < NPIX; p += 4) {
        float v = (g_F[(bb*NPIX + p)*DH + d] - mu) * rv;
        m = fmaxf(m, v);
    }
    __shared__ float shm[256];
    shm[threadIdx.x] = m; __syncthreads();
    if (pc == 0) {
        m = fmaxf(fmaxf(shm[d], shm[64+d]), fmaxf(shm[128+d], shm[192+d]));
        g_M[bb*DH + d] = m;
    }
}

// ---------------- final lin2 + elu ----------------
__global__ void final_kernel(const float* __restrict__ w, const float* __restrict__ b,
                             float* __restrict__ out) {
    int idx = blockIdx.x * blockDim.x + threadIdx.x;
    if (idx >= NB*10) return;
    int bb = idx / 10, j = idx % 10;
    float acc = b[j];
    #pragma unroll
    for (int d = 0; d < DH; d++) acc += g_M[bb*DH + d] * w[d*10 + j];
    out[idx] = eluf(acc);
}

extern "C" void kernel_launch(void* const* d_in, const int* in_sizes, int n_in,
                              void* d_out, int out_size) {
    const float* x       = (const float*)d_in[0];
    const float* conv1_w = (const float*)d_in[1];
    const float* conv1_b = (const float*)d_in[2];
    const float* conv2_w = (const float*)d_in[3];
    const float* conv2_b = (const float*)d_in[4];
    const float* kp_w    = (const float*)d_in[5];
    const float* kp_b    = (const float*)d_in[6];
    const float* qp_w    = (const float*)d_in[7];
    const float* qp_b    = (const float*)d_in[8];
    const float* vp_w    = (const float*)d_in[9];
    const float* vp_b    = (const float*)d_in[10];
    const float* klin_w  = (const float*)d_in[11];
    const float* klin_b  = (const float*)d_in[12];
    const float* qlin_w  = (const float*)d_in[13];
    const float* qlin_b  = (const float*)d_in[14];
    const float* alin_w  = (const float*)d_in[15];
    const float* alin_b  = (const float*)d_in[16];
    const float* knorm_g = (const float*)d_in[17];
    const float* knorm_b = (const float*)d_in[18];
    const float* qnorm_g = (const float*)d_in[19];
    const float* qnorm_b = (const float*)d_in[20];
    const float* vnorm_g = (const float*)d_in[21];
    const float* vnorm_b = (const float*)d_in[22];
    const float* lin1_w  = (const float*)d_in[23];
    const float* lin1_b  = (const float*)d_in[24];
    const float* lin2_w  = (const float*)d_in[25];
    const float* lin2_b  = (const float*)d_in[26];
    float* out = (float*)d_out;

    cudaFuncSetAttribute(logits_gemm_kernel, cudaFuncAttributeMaxDynamicSharedMemorySize, GEMM_SMEM);
    cudaFuncSetAttribute(gemm_kernel,        cudaFuncAttributeMaxDynamicSharedMemorySize, GEMM_SMEM);
    cudaFuncSetAttribute(e_gemm_kernel,      cudaFuncAttributeMaxDynamicSharedMemorySize, EGEMM_SMEM);
    cudaFuncSetAttribute(lin1_gemm_kernel,   cudaFuncAttributeMaxDynamicSharedMemorySize, E3GEMM_SMEM);
    cudaFuncSetAttribute(proj_gemm_kernel,   cudaFuncAttributeMaxDynamicSharedMemorySize, E3GEMM_SMEM);
    cudaFuncSetAttribute(conv2_gemm_kernel,  cudaFuncAttributeMaxDynamicSharedMemorySize, C2GEMM_SMEM);

    conv1_kernel<<<(NB*16*150*5 + 255)/256, 256>>>(x, conv1_w, conv1_b);
    im2col_coords_kernel<<<(EROWS*96 + 255)/256, 256>>>();
    prep_all_kernel<<<(PREP_TOT + 255)/256, 256>>>(alin_w, qlin_w, klin_w, lin1_w,
                                                   kp_w, qp_w, vp_w, conv2_w);
    conv2_gemm_kernel<<<EROWS/128, 256, C2GEMM_SMEM>>>(conv2_b);
    {
        dim3 g(EROWS/128, 12);                     // (298, 12)
        proj_gemm_kernel<<<g, 256, E3GEMM_SMEM>>>(kp_b, qp_b, vp_b);
    }
    {
        dim3 g(NB, 3);
        ln_stats_kernel<<<g, 512>>>();
    }
    {
        dim3 g(PER_B/1024, NB, 3);
        ln_apply_kernel<<<g, 256>>>(knorm_g, knorm_b, qnorm_g, qnorm_b, vnorm_g, vnorm_b);
    }
    {
        dim3 g(KPAD/128, MROWS/128);               // (5, 1192)
        logits_gemm_kernel<<<g, 128, GEMM_SMEM>>>(qlin_b, klin_b);
    }
    {
        dim3 g(KPAD/128, MROWS/128);               // (5, 1192)
        gemm_kernel<<<g, 128, GEMM_SMEM>>>(alin_b);
    }
    vtrans_kernel<<<NB*HEADS, 256>>>();
    softmax_kernel<<<MROWS/8, 256>>>();
    {
        dim3 g(5, NB*HEADS);                       // (5, 256)
        e_gemm_kernel<<<g, 256, EGEMM_SMEM>>>();
    }
    lin1_gemm_kernel<<<EROWS/128, 256, E3GEMM_SMEM>>>(lin1_b);
    ln2_kernel<<<NB, 256>>>();
    final_kernel<<<3, 256>>>(lin2_w, lin2_b, out);
}

// round 15
// speedup vs baseline: 1.4299x; 1.0565x over previous
#include <cuda_runtime.h>
#include <cuda_bf16.h>
#include <math.h>
#include <stdint.h>

#define NB 64
#define NPIX 596
#define HEADS 4
#define DH 64
#define PER_B (HEADS*NPIX*DH)   // 152576
#define MROWS (NB*HEADS*NPIX)   // 152576
#define EROWS (NB*NPIX)         // 38144
#define KPAD 640

// ---- tf32 gemm common ----
#define KC 32
#define NCH (KPAD/KC)           // 20
#define NCHF 19                 // flash e-gemm: ceil(596/32)
#define NCHL (128/KC)           // 4
#define NCH1 (256/KC)           // 8
#define NCHP (64/KC)            // 2
#define SKF 36
#define FBUF (128*SKF)
#define VFBUF (64*SKF)
#define G_BUF (2*FBUF)
#define GEMM_SMEM (2*G_BUF*4)                   // 73728
#define E_BUF (FBUF + VFBUF)
#define EGEMM_SMEM (2*E_BUF*4)                  // 55296
#define E3_BUF (FBUF + 2*VFBUF)
#define E3GEMM_SMEM (2*E3_BUF*4)                // 73728
#define C2_BUF (FBUF + 2*32*SKF)
#define C2GEMM_SMEM (2*C2_BUF*4)                // 55296

// ---------------- scratch ----------------
__device__ float g_conv1[NB*16*150*5];
__device__ float g_col[(size_t)EROWS*64];
__device__ float g_feats[(size_t)EROWS*64];
__device__ float g_K[NB*HEADS*NPIX*DH];
__device__ float g_Q[NB*HEADS*NPIX*DH];
__device__ float g_V[NB*HEADS*NPIX*DH];
__device__ float g_Wkqvh[768*64], g_Wkqvl[768*64];
__device__ float g_Wc2h[32*64],  g_Wc2l[32*64];
__device__ float g_W1th[64*256], g_W1tl[64*256];
__device__ float g_mu[3*NB], g_rv[3*NB];
__device__ float g_QKf[(size_t)MROWS*128];
__device__ float g_Wqkf[(size_t)KPAD*128];
__device__ float g_A[(size_t)MROWS*KPAD];
__device__ float g_Wf[(size_t)KPAD*KPAD];
__device__ float g_Vt[(size_t)NB*HEADS*DH*KPAD];
__device__ float g_S[(size_t)MROWS*NPIX + 64];   // +64 pad: flash tail reads past row end
__device__ float g_E[(size_t)EROWS*256];
__device__ float g_F[EROWS*DH];
__device__ float g_M[NB*DH];

__device__ __forceinline__ float eluf(float x) {
    return x > 0.f ? x : (__expf(x) - 1.f);
}
__device__ __forceinline__ float tf32r(float x) {
    uint32_t u;
    asm("cvt.rna.tf32.f32 %0, %1;" : "=r"(u) : "f"(x));
    return __uint_as_float(u);
}

// ---- mma.sync tf32 ----
__device__ __forceinline__ void mma_tf32(float* c, const float* a, float b0, float b1) {
    asm volatile(
        "mma.sync.aligned.m16n8k8.row.col.f32.tf32.tf32.f32 "
        "{%0,%1,%2,%3}, {%4,%5,%6,%7}, {%8,%9}, {%0,%1,%2,%3};"
        : "+f"(c[0]), "+f"(c[1]), "+f"(c[2]), "+f"(c[3])
        : "r"(__float_as_uint(a[0])), "r"(__float_as_uint(a[1])),
          "r"(__float_as_uint(a[2])), "r"(__float_as_uint(a[3])),
          "r"(__float_as_uint(b0)), "r"(__float_as_uint(b1)));
}
// ---- cp.async ----
__device__ __forceinline__ void cp16(void* smem, const void* gmem) {
    uint32_t s = (uint32_t)__cvta_generic_to_shared(smem);
    asm volatile("cp.async.cg.shared.global [%0], [%1], 16;" :: "r"(s), "l"(gmem));
}
#define CP_COMMIT() asm volatile("cp.async.commit_group;" ::: "memory")
#define CP_WAIT1()  asm volatile("cp.async.wait_group 1;" ::: "memory")
#define CP_WAIT0()  asm volatile("cp.async.wait_group 0;" ::: "memory")

// ---------------- conv1 + relu ----------------
__global__ void conv1_kernel(const float* __restrict__ x,
                             const float* __restrict__ w,
                             const float* __restrict__ b) {
    int idx = blockIdx.x * blockDim.x + threadIdx.x;
    if (idx >= NB*16*150*5) return;
    int ow = idx % 5;
    int oh = (idx / 5) % 150;
    int co = (idx / (5*150)) % 16;
    int bb = idx / (5*150*16);
    float acc = b[co];
    #pragma unroll
    for (int ci = 0; ci < 4; ci++)
        #pragma unroll
        for (int kh = 0; kh < 2; kh++)
            #pragma unroll
            for (int kw = 0; kw < 2; kw++)
                acc += x[((bb*4+ci)*151 + oh+kh)*6 + ow+kw] *
                       w[((co*4+ci)*2 + kh)*2 + kw];
    g_conv1[idx] = fmaxf(acc, 0.f);
}

// ---------------- im2col + coords (merged) ----------------
__global__ void im2col_coords_kernel() {
    int idx = blockIdx.x * blockDim.x + threadIdx.x;
    if (idx < EROWS*64) {
        int c = idx & 63;
        int bp = idx >> 6;
        int p = bp % NPIX, bb = bp / NPIX;
        int oh = p / 4, ow = p % 4;
        int ci = c >> 2, kh = (c >> 1) & 1, kw = c & 1;
        g_col[idx] = g_conv1[((bb*16+ci)*150 + oh+kh)*5 + ow+kw];
        return;
    }
    idx -= EROWS*64;
    if (idx < EROWS*32) {
        int c = 32 + (idx & 31);
        int bp = idx >> 5;
        int p = bp % NPIX;
        float v = 0.f;
        if (c == 32) v = (float)(p % 4) / 4.f;
        else if (c == 33) v = (float)(p / 4) / 149.f;
        g_feats[(size_t)bp*64 + c] = v;
    }
}

// ---------------- conv2 GEMM (tf32 3-term, pre-split W): feats[:, :32] ----------------
__global__ __launch_bounds__(256, 2) void conv2_gemm_kernel(const float* __restrict__ b2) {
    extern __shared__ float fsm[];
    int tid = threadIdx.x;
    int lane = tid & 31;
    int wid = tid >> 5;
    int g = lane >> 2, tig = lane & 3;
    size_t m0 = (size_t)blockIdx.x * 128;

    float acc[4][4];
    #pragma unroll
    for (int ni = 0; ni < 4; ni++)
        #pragma unroll
        for (int k = 0; k < 4; k++) acc[ni][k] = 0.f;

    auto loadT = [&](float* b, int kc) {
        #pragma unroll
        for (int j = 0; j < 4; j++) {
            int idx = tid + j*256;
            int r = idx >> 3, q = idx & 7;
            cp16(b + r*SKF + q*4, g_col + (m0 + r)*64 + kc + q*4);
        }
        {
            int r = tid >> 3, q = tid & 7;
            cp16(b + FBUF + r*SKF + q*4, g_Wc2h + r*64 + kc + q*4);
            cp16(b + FBUF + 32*SKF + r*SKF + q*4, g_Wc2l + r*64 + kc + q*4);
        }
    };

    loadT(fsm, 0);
    CP_COMMIT();
    for (int ch = 0; ch < NCHP; ch++) {
        if (ch + 1 < NCHP) {
            loadT(fsm + ((ch+1)&1)*C2_BUF, (ch+1)*KC);
            CP_COMMIT();
            CP_WAIT1();
        } else {
            CP_WAIT0();
        }
        __syncthreads();
        const float* sE = fsm + (ch&1)*C2_BUF;
        const float* sWh = sE + FBUF;
        const float* sWl = sWh + 32*SKF;
        #pragma unroll
        for (int ks = 0; ks < 4; ks++) {
            int ko = ks*8;
            float raw[4], eh[4], el[4];
            const float* ar = sE + (wid*16 + g)*SKF + ko + tig;
            raw[0] = ar[0];
            raw[1] = ar[8*SKF];
            raw[2] = ar[4];
            raw[3] = ar[8*SKF + 4];
            #pragma unroll
            for (int q = 0; q < 4; q++) {
                eh[q] = tf32r(raw[q]);
                el[q] = tf32r(raw[q] - eh[q]);
            }
            #pragma unroll
            for (int nsub = 0; nsub < 4; nsub++) {
                const float* bh = sWh + (nsub*8 + g)*SKF + ko + tig;
                const float* bl = sWl + (nsub*8 + g)*SKF + ko + tig;
                float wh0 = bh[0], wh1 = bh[4];
                float wl0 = bl[0], wl1 = bl[4];
                mma_tf32(acc[nsub], eh, wh0, wh1);
                mma_tf32(acc[nsub], eh, wl0, wl1);
                mma_tf32(acc[nsub], el, wh0, wh1);
            }
        }
        __syncthreads();
    }

    #pragma unroll
    for (int nsub = 0; nsub < 4; nsub++) {
        int n = nsub*8 + tig*2;
        float b0 = b2[n], b1 = b2[n+1];
        #pragma unroll
        for (int half = 0; half < 2; half++) {
            size_t m = m0 + wid*16 + g + half*8;
            float2 o;
            o.x = fmaxf(acc[nsub][2*half]   + b0, 0.f);
            o.y = fmaxf(acc[nsub][2*half+1] + b1, 0.f);
            *(float2*)(g_feats + m*64 + n) = o;
        }
    }
}

// ---------------- proj GEMM (tf32 3-term, pre-split W): [K|Q|V] ----------------
__global__ __launch_bounds__(256, 2) void proj_gemm_kernel(
    const float* __restrict__ kb, const float* __restrict__ qb,
    const float* __restrict__ vb) {
    extern __shared__ float fsm[];
    int tid = threadIdx.x;
    int lane = tid & 31;
    int wid = tid >> 5;
    int g = lane >> 2, tig = lane & 3;
    size_t m0 = (size_t)blockIdx.x * 128;
    int n0 = blockIdx.y * 64;

    float acc[8][4];
    #pragma unroll
    for (int ni = 0; ni < 8; ni++)
        #pragma unroll
        for (int k = 0; k < 4; k++) acc[ni][k] = 0.f;

    auto loadT = [&](float* b, int kc) {
        #pragma unroll
        for (int j = 0; j < 4; j++) {
            int idx = tid + j*256;
            int r = idx >> 3, q = idx & 7;
            cp16(b + r*SKF + q*4, g_feats + (m0 + r)*64 + kc + q*4);
        }
        #pragma unroll
        for (int j = 0; j < 2; j++) {
            int idx = tid + j*256;
            int r = idx >> 3, q = idx & 7;
            cp16(b + FBUF + r*SKF + q*4, g_Wkqvh + (n0 + r)*64 + kc + q*4);
            cp16(b + FBUF + VFBUF + r*SKF + q*4, g_Wkqvl + (n0 + r)*64 + kc + q*4);
        }
    };

    loadT(fsm, 0);
    CP_COMMIT();
    for (int ch = 0; ch < NCHP; ch++) {
        if (ch + 1 < NCHP) {
            loadT(fsm + ((ch+1)&1)*E3_BUF, (ch+1)*KC);
            CP_COMMIT();
            CP_WAIT1();
        } else {
            CP_WAIT0();
        }
        __syncthreads();
        const float* sE = fsm + (ch&1)*E3_BUF;
        const float* sWh = sE + FBUF;
        const float* sWl = sWh + VFBUF;
        #pragma unroll
        for (int ks = 0; ks < 4; ks++) {
            int ko = ks*8;
            float raw[4], eh[4], el[4];
            const float* ar = sE + (wid*16 + g)*SKF + ko + tig;
            raw[0] = ar[0];
            raw[1] = ar[8*SKF];
            raw[2] = ar[4];
            raw[3] = ar[8*SKF + 4];
            #pragma unroll
            for (int q = 0; q < 4; q++) {
                eh[q] = tf32r(raw[q]);
                el[q] = tf32r(raw[q] - eh[q]);
            }
            #pragma unroll
            for (int nsub = 0; nsub < 8; nsub++) {
                const float* bh = sWh + (nsub*8 + g)*SKF + ko + tig;
                const float* bl = sWl + (nsub*8 + g)*SKF + ko + tig;
                float wh0 = bh[0], wh1 = bh[4];
                float wl0 = bl[0], wl1 = bl[4];
                mma_tf32(acc[nsub], eh, wh0, wh1);
                mma_tf32(acc[nsub], eh, wl0, wl1);
                mma_tf32(acc[nsub], el, wh0, wh1);
            }
        }
        __syncthreads();
    }

    int mloc[2], bbv[2], pv[2];
    #pragma unroll
    for (int half = 0; half < 2; half++) {
        mloc[half] = (int)(m0 + wid*16 + g + half*8);
        bbv[half] = mloc[half] / NPIX;
        pv[half]  = mloc[half] % NPIX;
    }
    #pragma unroll
    for (int nsub = 0; nsub < 8; nsub++) {
        int n = n0 + nsub*8 + tig*2;
        int t = n >> 8;
        int hd = n & 255;
        int h = hd >> 6, d = hd & 63;
        const float* B = t == 0 ? kb : t == 1 ? qb : vb;
        float* O = t == 0 ? g_K : t == 1 ? g_Q : g_V;
        float b0 = B[hd], b1 = B[hd+1];
        #pragma unroll
        for (int half = 0; half < 2; half++) {
            float2 o;
            o.x = acc[nsub][2*half]   + b0;
            o.y = acc[nsub][2*half+1] + b1;
            *(float2*)(O + ((size_t)(bbv[half]*HEADS + h)*NPIX + pv[half])*DH + d) = o;
        }
    }
}

// ---------------- LN stats (512 thr, float4) ----------------
__global__ __launch_bounds__(512) void ln_stats_kernel() {
    int bb = blockIdx.x, t = blockIdx.y;
    const float4* base = (const float4*)((t==0 ? g_K : t==1 ? g_Q : g_V) + bb*PER_B);
    const int n4 = PER_B/4;
    float s = 0.f, ss = 0.f;
    for (int i = threadIdx.x; i < n4; i += 512) {
        float4 v = base[i];
        s  += v.x + v.y + v.z + v.w;
        ss += v.x*v.x + v.y*v.y + v.z*v.z + v.w*v.w;
    }
    __shared__ double sh[512], sh2[512];
    sh[threadIdx.x] = (double)s; sh2[threadIdx.x] = (double)ss; __syncthreads();
    for (int o = 256; o; o >>= 1) {
        if (threadIdx.x < o) { sh[threadIdx.x] += sh[threadIdx.x+o]; sh2[threadIdx.x] += sh2[threadIdx.x+o]; }
        __syncthreads();
    }
    if (threadIdx.x == 0) {
        double m = sh[0] / (double)PER_B;
        double var = sh2[0] / (double)PER_B - m*m;
        g_mu[t*NB+bb] = (float)m;
        g_rv[t*NB+bb] = (float)(1.0 / sqrt(var + 1e-5));
    }
}

// ---------------- LN apply: Q,K -> tf32-rounded QK concat; V -> fp32 ----------------
__global__ void ln_apply_kernel(const float* __restrict__ kg, const float* __restrict__ kb,
                                const float* __restrict__ qg, const float* __restrict__ qb,
                                const float* __restrict__ vg, const float* __restrict__ vb) {
    int t = blockIdx.z;
    int bb = blockIdx.y;
    const float* base = (t==0 ? g_K : t==1 ? g_Q : g_V) + bb*PER_B;
    const float* g = t==0 ? kg : t==1 ? qg : vg;
    const float* be = t==0 ? kb : t==1 ? qb : vb;
    int off = (blockIdx.x*256 + threadIdx.x)*4;
    float mu = g_mu[t*NB+bb], rv = g_rv[t*NB+bb];
    float4 v  = *(const float4*)(base + off);
    float4 gg = *(const float4*)(g + off);
    float4 bv = *(const float4*)(be + off);
    float4 r;
    r.x = (v.x - mu)*rv*gg.x + bv.x;
    r.y = (v.y - mu)*rv*gg.y + bv.y;
    r.z = (v.z - mu)*rv*gg.z + bv.z;
    r.w = (v.w - mu)*rv*gg.w + bv.w;
    if (t == 2) {
        *(float4*)(g_V + bb*PER_B + off) = r;
    } else {
        int d = off & 63;
        int hp = off >> 6;
        size_t row = (size_t)bb*HEADS*NPIX + hp;
        int col = d + (t == 0 ? 64 : 0);
        float4 o;
        o.x = tf32r(r.x); o.y = tf32r(r.y); o.z = tf32r(r.z); o.w = tf32r(r.w);
        *(float4*)(g_QKf + row*128 + col) = o;
    }
}

// ---------------- V transpose (tf32-rounded): Vt[bh][d][p_pad] ----------------
__global__ void vtrans_kernel() {
    __shared__ float tile[32][65];
    int bhid = blockIdx.x;
    const float* Vb = g_V + (size_t)bhid*NPIX*DH;
    int t = threadIdx.x;
    for (int pt = 0; pt < 20; pt++) {
        int p0 = pt*32;
        for (int i = t; i < 32*64; i += 256) {
            int r = i >> 6, c = i & 63;
            tile[r][c] = (p0 + r < NPIX) ? Vb[(p0 + r)*DH + c] : 0.f;
        }
        __syncthreads();
        for (int i = t; i < 64*32; i += 256) {
            int d = i >> 5, pp = i & 31;
            g_Vt[((size_t)bhid*DH + d)*KPAD + p0 + pp] = tf32r(tile[pp][d]);
        }
        __syncthreads();
    }
}

// ---------------- merged weight prep ----------------
__global__ void prep_all_kernel(const float* __restrict__ alw,
                                const float* __restrict__ qlw,
                                const float* __restrict__ klw,
                                const float* __restrict__ w1,
                                const float* __restrict__ kpw,
                                const float* __restrict__ qpw,
                                const float* __restrict__ vpw,
                                const float* __restrict__ c2w) {
    int idx = blockIdx.x*256 + threadIdx.x;
    if (idx < KPAD*KPAD) {
        int k = idx / KPAD, n = idx % KPAD;
        float v = (k < NPIX && n < NPIX) ? alw[k*NPIX + n] : 0.f;
        g_Wf[(size_t)n*KPAD + k] = tf32r(v);
        return;
    }
    idx -= KPAD*KPAD;
    if (idx < KPAD*128) {
        int n = idx >> 7, k = idx & 127;
        float v = 0.f;
        if (n < NPIX) v = (k < 64) ? qlw[k*NPIX + n] : klw[(k-64)*NPIX + n];
        g_Wqkf[(size_t)n*128 + k] = tf32r(v);
        return;
    }
    idx -= KPAD*128;
    if (idx < 64*256) {
        int d = idx >> 8, c = idx & 255;
        float v = w1[c*64 + d];
        float h = tf32r(v);
        g_W1th[d*256 + c] = h;
        g_W1tl[d*256 + c] = tf32r(v - h);
        return;
    }
    idx -= 64*256;
    if (idx < 768*64) {
        int n = idx >> 6, c = idx & 63;
        int t = n >> 8, hd = n & 255;
        const float* W = t == 0 ? kpw : t == 1 ? qpw : vpw;
        float v = (c < 34) ? W[c*256 + hd] : 0.f;
        float h = tf32r(v);
        g_Wkqvh[n*64 + c] = h;
        g_Wkqvl[n*64 + c] = tf32r(v - h);
        return;
    }
    idx -= 768*64;
    if (idx < 32*64) {
        int n = idx >> 6, c = idx & 63;
        int ci = c >> 2, kh = (c >> 1) & 1, kw = c & 1;
        float v = c2w[((n*16+ci)*2 + kh)*2 + kw];
        float h = tf32r(v);
        g_Wc2h[n*64 + c] = h;
        g_Wc2l[n*64 + c] = tf32r(v - h);
    }
}
#define PREP_TOT (KPAD*KPAD + KPAD*128 + 64*256 + 768*64 + 32*64)

// ---------------- pipelined cp.async tile loaders (fp32, 128 thr) ----------------
__device__ __forceinline__ void cp_ftile_t128(float* dst, const float* g,
                                              size_t row0, int kc, int tid, int gstride) {
    #pragma unroll
    for (int j = 0; j < 8; j++) {
        int idx = tid + j*128;
        int r = idx >> 3, q = idx & 7;
        cp16(dst + r*SKF + q*4, g + (row0 + r)*(size_t)gstride + kc + q*4);
    }
}

// ---------------- tf32 GEMM inner step: 4 warps, warp tile 64x64 ----------------
__device__ __forceinline__ void tf32_step4(const float* sA, const float* sW, int ko,
                                           int wm, int wn, int g, int tig,
                                           float acc[4][8][4]) {
    float af[4][4];
    #pragma unroll
    for (int mi = 0; mi < 4; mi++) {
        const float* ar = sA + (wm*64 + mi*16 + g)*SKF + ko + tig;
        af[mi][0] = ar[0];
        af[mi][1] = ar[8*SKF];
        af[mi][2] = ar[4];
        af[mi][3] = ar[8*SKF + 4];
    }
    #pragma unroll
    for (int nsub = 0; nsub < 8; nsub++) {
        const float* br = sW + (wn*64 + nsub*8 + g)*SKF + ko + tig;
        float b0 = br[0], b1 = br[4];
        #pragma unroll
        for (int mi = 0; mi < 4; mi++)
            mma_tf32(acc[mi][nsub], af[mi], b0, b1);
    }
}

// ---------------- logits GEMM (tf32, 128 thr, occ 3): A = elu(QK @ Wqk^T + bias) ----------------
__global__ __launch_bounds__(128, 3) void logits_gemm_kernel(
    const float* __restrict__ qlb, const float* __restrict__ klb) {
    extern __shared__ float fsm[];
    int tid = threadIdx.x;
    int lane = tid & 31;
    int wid = tid >> 5;
    int wm = wid & 1, wn = wid >> 1;
    int g = lane >> 2, tig = lane & 3;
    int n0 = blockIdx.x * 128;
    size_t m0 = (size_t)blockIdx.y * 128;

    float acc[4][8][4];
    #pragma unroll
    for (int mi = 0; mi < 4; mi++)
        #pragma unroll
        for (int ni = 0; ni < 8; ni++)
            #pragma unroll
            for (int k = 0; k < 4; k++) acc[mi][ni][k] = 0.f;

    {
        float* b = fsm;
        cp_ftile_t128(b,        g_QKf,  m0, 0, tid, 128);
        cp_ftile_t128(b + FBUF, g_Wqkf, n0, 0, tid, 128);
        CP_COMMIT();
    }
    for (int ch = 0; ch < NCHL; ch++) {
        if (ch + 1 < NCHL) {
            float* b = fsm + ((ch+1)&1)*G_BUF;
            int kc = (ch+1)*KC;
            cp_ftile_t128(b,        g_QKf,  m0, kc, tid, 128);
            cp_ftile_t128(b + FBUF, g_Wqkf, n0, kc, tid, 128);
            CP_COMMIT();
            CP_WAIT1();
        } else {
            CP_WAIT0();
        }
        __syncthreads();
        const float* sA = fsm + (ch&1)*G_BUF;
        const float* sW = sA + FBUF;
        #pragma unroll
        for (int ks = 0; ks < 4; ks++)
            tf32_step4(sA, sW, ks*8, wm, wn, g, tig, acc);
        __syncthreads();
    }

    #pragma unroll
    for (int mi = 0; mi < 4; mi++) {
        #pragma unroll
        for (int nsub = 0; nsub < 8; nsub++) {
            int n = n0 + wn*64 + nsub*8 + tig*2;
            float b0 = (n < NPIX)   ? qlb[n] + klb[n]     : 0.f;
            float b1 = (n+1 < NPIX) ? qlb[n+1] + klb[n+1] : 0.f;
            #pragma unroll
            for (int half = 0; half < 2; half++) {
                size_t m = m0 + wm*64 + mi*16 + g + half*8;
                float2 o;
                o.x = tf32r(eluf(acc[mi][nsub][2*half]   + b0));
                o.y = tf32r(eluf(acc[mi][nsub][2*half+1] + b1));
                *(float2*)(g_A + m*KPAD + n) = o;
            }
        }
    }
}

// ---------------- main GEMM (tf32, 128 thr, occ 3): S = A @ W^T + alb ----------------
__global__ __launch_bounds__(128, 3) void gemm_kernel(const float* __restrict__ alb) {
    extern __shared__ float fsm[];
    int tid = threadIdx.x;
    int lane = tid & 31;
    int wid = tid >> 5;
    int wm = wid & 1, wn = wid >> 1;
    int g = lane >> 2, tig = lane & 3;
    int n0 = blockIdx.x * 128;
    size_t m0 = (size_t)blockIdx.y * 128;

    float acc[4][8][4];
    #pragma unroll
    for (int mi = 0; mi < 4; mi++)
        #pragma unroll
        for (int ni = 0; ni < 8; ni++)
            #pragma unroll
            for (int k = 0; k < 4; k++) acc[mi][ni][k] = 0.f;

    {
        float* b = fsm;
        cp_ftile_t128(b,        g_A,  m0, 0, tid, KPAD);
        cp_ftile_t128(b + FBUF, g_Wf, n0, 0, tid, KPAD);
        CP_COMMIT();
    }
    for (int ch = 0; ch < NCH; ch++) {
        if (ch + 1 < NCH) {
            float* b = fsm + ((ch+1)&1)*G_BUF;
            int kc = (ch+1)*KC;
            cp_ftile_t128(b,        g_A,  m0, kc, tid, KPAD);
            cp_ftile_t128(b + FBUF, g_Wf, n0, kc, tid, KPAD);
            CP_COMMIT();
            CP_WAIT1();
        } else {
            CP_WAIT0();
        }
        __syncthreads();
        const float* sA = fsm + (ch&1)*G_BUF;
        const float* sW = sA + FBUF;
        #pragma unroll
        for (int ks = 0; ks < 4; ks++)
            tf32_step4(sA, sW, ks*8, wm, wn, g, tig, acc);
        __syncthreads();
    }

    #pragma unroll
    for (int mi = 0; mi < 4; mi++) {
        #pragma unroll
        for (int nsub = 0; nsub < 8; nsub++) {
            int n = n0 + wn*64 + nsub*8 + tig*2;
            #pragma unroll
            for (int half = 0; half < 2; half++) {
                size_t m = m0 + wm*64 + mi*16 + g + half*8;
                if (n + 1 < NPIX) {
                    float2 o;
                    o.x = acc[mi][nsub][2*half]   + alb[n];
                    o.y = acc[mi][nsub][2*half+1] + alb[n+1];
                    *(float2*)(g_S + m*NPIX + n) = o;
                } else if (n < NPIX) {
                    g_S[m*NPIX + n] = acc[mi][nsub][2*half] + alb[n];
                }
            }
        }
    }
}

// ---------------- flash E GEMM: online softmax over S, E = softmax(S) @ Vt^T ----------------
__global__ __launch_bounds__(256, 2) void flash_e_gemm_kernel() {
    extern __shared__ float fsm[];
    int tid = threadIdx.x;
    int lane = tid & 31;
    int wid = tid >> 5;
    int g = lane >> 2, tig = lane & 3;
    int mt = blockIdx.x;
    int bhid = blockIdx.y;
    int p00 = mt * 128;
    int bb = bhid >> 2, h = bhid & 3;

    float acc[8][4];
    #pragma unroll
    for (int ni = 0; ni < 8; ni++)
        #pragma unroll
        for (int k = 0; k < 4; k++) acc[ni][k] = 0.f;
    float mrun0 = -1e30f, mrun1 = -1e30f;
    float srun0 = 0.f, srun1 = 0.f;

    auto loadT = [&](float* b, int kc) {
        #pragma unroll
        for (int j = 0; j < 4; j++) {
            int idx = tid + j*256;
            int r = idx >> 3, q = idx & 7;
            int p = p00 + r; if (p > NPIX-1) p = NPIX-1;
            cp16(b + r*SKF + q*4, g_S + (size_t)((size_t)bhid*NPIX + p)*NPIX + kc + q*4);
        }
        #pragma unroll
        for (int j = 0; j < 2; j++) {
            int idx = tid + j*256;
            int r = idx >> 3, q = idx & 7;
            cp16(b + FBUF + r*SKF + q*4, g_Vt + ((size_t)bhid*DH + r)*KPAD + kc + q*4);
        }
    };

    loadT(fsm, 0);
    CP_COMMIT();
    for (int ch = 0; ch < NCHF; ch++) {
        if (ch + 1 < NCHF) {
            loadT(fsm + ((ch+1)&1)*E_BUF, (ch+1)*KC);
            CP_COMMIT();
            CP_WAIT1();
        } else {
            CP_WAIT0();
        }
        __syncthreads();
        const float* sS = fsm + (ch&1)*E_BUF;
        const float* sV = sS + FBUF;
        int kc = ch*KC;
        const float* arow = sS + (wid*16 + g)*SKF + tig;

        // pass 1: chunk max per row
        float cm0 = -1e30f, cm1 = -1e30f;
        #pragma unroll
        for (int ks = 0; ks < 4; ks++) {
            int c0 = kc + ks*8 + tig;
            const float* ar = arow + ks*8;
            float v00 = (c0 < NPIX)     ? ar[0]          : -1e30f;
            float v01 = (c0 + 4 < NPIX) ? ar[4]          : -1e30f;
            float v10 = (c0 < NPIX)     ? ar[8*SKF]      : -1e30f;
            float v11 = (c0 + 4 < NPIX) ? ar[8*SKF + 4]  : -1e30f;
            cm0 = fmaxf(cm0, fmaxf(v00, v01));
            cm1 = fmaxf(cm1, fmaxf(v10, v11));
        }
        cm0 = fmaxf(cm0, __shfl_xor_sync(0xffffffffu, cm0, 1));
        cm0 = fmaxf(cm0, __shfl_xor_sync(0xffffffffu, cm0, 2));
        cm1 = fmaxf(cm1, __shfl_xor_sync(0xffffffffu, cm1, 1));
        cm1 = fmaxf(cm1, __shfl_xor_sync(0xffffffffu, cm1, 2));
        float mn0 = fmaxf(mrun0, cm0);
        float mn1 = fmaxf(mrun1, cm1);
        float f0 = __expf(mrun0 - mn0);
        float f1 = __expf(mrun1 - mn1);
        mrun0 = mn0; mrun1 = mn1;
        srun0 *= f0; srun1 *= f1;
        #pragma unroll
        for (int nsub = 0; nsub < 8; nsub++) {
            acc[nsub][0] *= f0; acc[nsub][1] *= f0;
            acc[nsub][2] *= f1; acc[nsub][3] *= f1;
        }

        // pass 2: exp + mma + sum
        float cs0 = 0.f, cs1 = 0.f;
        #pragma unroll
        for (int ks = 0; ks < 4; ks++) {
            int c0 = kc + ks*8 + tig;
            const float* ar = arow + ks*8;
            float v00 = (c0 < NPIX)     ? ar[0]          : -1e30f;
            float v01 = (c0 + 4 < NPIX) ? ar[4]          : -1e30f;
            float v10 = (c0 < NPIX)     ? ar[8*SKF]      : -1e30f;
            float v11 = (c0 + 4 < NPIX) ? ar[8*SKF + 4]  : -1e30f;
            float e00 = __expf(v00 - mrun0);
            float e01 = __expf(v01 - mrun0);
            float e10 = __expf(v10 - mrun1);
            float e11 = __expf(v11 - mrun1);
            cs0 += e00 + e01;
            cs1 += e10 + e11;
            float af[4];
            af[0] = tf32r(e00); af[1] = tf32r(e10);
            af[2] = tf32r(e01); af[3] = tf32r(e11);
            #pragma unroll
            for (int nsub = 0; nsub < 8; nsub++) {
                const float* br = sV + (nsub*8 + g)*SKF + ks*8 + tig;
                mma_tf32(acc[nsub], af, br[0], br[4]);
            }
        }
        cs0 += __shfl_xor_sync(0xffffffffu, cs0, 1);
        cs0 += __shfl_xor_sync(0xffffffffu, cs0, 2);
        cs1 += __shfl_xor_sync(0xffffffffu, cs1, 1);
        cs1 += __shfl_xor_sync(0xffffffffu, cs1, 2);
        srun0 += cs0; srun1 += cs1;
        __syncthreads();
    }

    float inv0 = 1.f / srun0;
    float inv1 = 1.f / srun1;
    #pragma unroll
    for (int nsub = 0; nsub < 8; nsub++) {
        int d = nsub*8 + tig*2;
        #pragma unroll
        for (int half = 0; half < 2; half++) {
            int p = p00 + wid*16 + g + half*8;
            if (p < NPIX) {
                float inv = half == 0 ? inv0 : inv1;
                float2 o;
                o.x = acc[nsub][2*half]   * inv;
                o.y = acc[nsub][2*half+1] * inv;
                *(float2*)(g_E + ((size_t)bb*NPIX + p)*256 + h*DH + d) = o;
            }
        }
    }
}

// ---------------- lin1 GEMM (tf32, 3-term, pre-split W): F = relu(E @ W1t^T + b) ----------------
__global__ __launch_bounds__(256, 2) void lin1_gemm_kernel(const float* __restrict__ b1) {
    extern __shared__ float fsm[];
    int tid = threadIdx.x;
    int lane = tid & 31;
    int wid = tid >> 5;
    int g = lane >> 2, tig = lane & 3;
    size_t m0 = (size_t)blockIdx.x * 128;

    float acc[8][4];
    #pragma unroll
    for (int ni = 0; ni < 8; ni++)
        #pragma unroll
        for (int k = 0; k < 4; k++) acc[ni][k] = 0.f;

    auto loadT = [&](float* b, int kc) {
        #pragma unroll
        for (int j = 0; j < 4; j++) {
            int idx = tid + j*256;
            int r = idx >> 3, q = idx & 7;
            cp16(b + r*SKF + q*4, g_E + (m0 + r)*256 + kc + q*4);
        }
        #pragma unroll
        for (int j = 0; j < 2; j++) {
            int idx = tid + j*256;
            int r = idx >> 3, q = idx & 7;
            cp16(b + FBUF + r*SKF + q*4, g_W1th + r*256 + kc + q*4);
            cp16(b + FBUF + VFBUF + r*SKF + q*4, g_W1tl + r*256 + kc + q*4);
        }
    };

    loadT(fsm, 0);
    CP_COMMIT();
    for (int ch = 0; ch < NCH1; ch++) {
        if (ch + 1 < NCH1) {
            loadT(fsm + ((ch+1)&1)*E3_BUF, (ch+1)*KC);
            CP_COMMIT();
            CP_WAIT1();
        } else {
            CP_WAIT0();
        }
        __syncthreads();
        const float* sE = fsm + (ch&1)*E3_BUF;
        const float* sWh = sE + FBUF;
        const float* sWl = sWh + VFBUF;
        #pragma unroll
        for (int ks = 0; ks < 4; ks++) {
            int ko = ks*8;
            float raw[4], eh[4], el[4];
            const float* ar = sE + (wid*16 + g)*SKF + ko + tig;
            raw[0] = ar[0];
            raw[1] = ar[8*SKF];
            raw[2] = ar[4];
            raw[3] = ar[8*SKF + 4];
            #pragma unroll
            for (int q = 0; q < 4; q++) {
                eh[q] = tf32r(raw[q]);
                el[q] = tf32r(raw[q] - eh[q]);
            }
            #pragma unroll
            for (int nsub = 0; nsub < 8; nsub++) {
                const float* bh = sWh + (nsub*8 + g)*SKF + ko + tig;
                const float* bl = sWl + (nsub*8 + g)*SKF + ko + tig;
                float wh0 = bh[0], wh1 = bh[4];
                float wl0 = bl[0], wl1 = bl[4];
                mma_tf32(acc[nsub], eh, wh0, wh1);
                mma_tf32(acc[nsub], eh, wl0, wl1);
                mma_tf32(acc[nsub], el, wh0, wh1);
            }
        }
        __syncthreads();
    }

    #pragma unroll
    for (int nsub = 0; nsub < 8; nsub++) {
        int d = nsub*8 + tig*2;
        float bb0 = b1[d], bb1 = b1[d+1];
        #pragma unroll
        for (int half = 0; half < 2; half++) {
            size_t m = m0 + wid*16 + g + half*8;
            float2 o;
            o.x = fmaxf(acc[nsub][2*half]   + bb0, 0.f);
            o.y = fmaxf(acc[nsub][2*half+1] + bb1, 0.f);
            *(float2*)(g_F + m*DH + d) = o;
        }
    }
}

// ---------------- LN2 (merged stats + apply + max) ----------------
__global__ __launch_bounds__(256) void ln2_kernel() {
    int bb = blockIdx.x;
    const float4* base = (const float4*)(g_F + bb*NPIX*DH);
    const int n4 = NPIX*DH/4;
    float s = 0.f, ss = 0.f;
    for (int i = threadIdx.x; i < n4; i += 256) {
        float4 v = base[i];
        s  += v.x + v.y + v.z + v.w;
        ss += v.x*v.x + v.y*v.y + v.z*v.z + v.w*v.w;
    }
    __shared__ double sh[256], sh2[256];
    __shared__ float smu, srv;
    sh[threadIdx.x] = (double)s; sh2[threadIdx.x] = (double)ss; __syncthreads();
    for (int o = 128; o; o >>= 1) {
        if (threadIdx.x < o) { sh[threadIdx.x] += sh[threadIdx.x+o]; sh2[threadIdx.x] += sh2[threadIdx.x+o]; }
        __syncthreads();
    }
    if (threadIdx.x == 0) {
        const int n = NPIX*DH;
        double m = sh[0] / (double)n;
        double var = sh2[0] / (double)n - m*m;
        smu = (float)m;
        srv = (float)(1.0 / sqrt(var + 1e-5));
    }
    __syncthreads();
    float mu = smu, rv = srv;
    int d = threadIdx.x & 63, pc = threadIdx.x >> 6;
    float m = -1e30f;
    for (int p = pc; p < NPIX; p += 4) {
        float v = (g_F[(bb*NPIX + p)*DH + d] - mu) * rv;
        m = fmaxf(m, v);
    }
    __shared__ float shm[256];
    shm[threadIdx.x] = m; __syncthreads();
    if (pc == 0) {
        m = fmaxf(fmaxf(shm[d], shm[64+d]), fmaxf(shm[128+d], shm[192+d]));
        g_M[bb*DH + d] = m;
    }
}

// ---------------- final lin2 + elu ----------------
__global__ void final_kernel(const float* __restrict__ w, const float* __restrict__ b,
                             float* __restrict__ out) {
    int idx = blockIdx.x * blockDim.x + threadIdx.x;
    if (idx >= NB*10) return;
    int bb = idx / 10, j = idx % 10;
    float acc = b[j];
    #pragma unroll
    for (int d = 0; d < DH; d++) acc += g_M[bb*DH + d] * w[d*10 + j];
    out[idx] = eluf(acc);
}

extern "C" void kernel_launch(void* const* d_in, const int* in_sizes, int n_in,
                              void* d_out, int out_size) {
    const float* x       = (const float*)d_in[0];
    const float* conv1_w = (const float*)d_in[1];
    const float* conv1_b = (const float*)d_in[2];
    const float* conv2_w = (const float*)d_in[3];
    const float* conv2_b = (const float*)d_in[4];
    const float* kp_w    = (const float*)d_in[5];
    const float* kp_b    = (const float*)d_in[6];
    const float* qp_w    = (const float*)d_in[7];
    const float* qp_b    = (const float*)d_in[8];
    const float* vp_w    = (const float*)d_in[9];
    const float* vp_b    = (const float*)d_in[10];
    const float* klin_w  = (const float*)d_in[11];
    const float* klin_b  = (const float*)d_in[12];
    const float* qlin_w  = (const float*)d_in[13];
    const float* qlin_b  = (const float*)d_in[14];
    const float* alin_w  = (const float*)d_in[15];
    const float* alin_b  = (const float*)d_in[16];
    const float* knorm_g = (const float*)d_in[17];
    const float* knorm_b = (const float*)d_in[18];
    const float* qnorm_g = (const float*)d_in[19];
    const float* qnorm_b = (const float*)d_in[20];
    const float* vnorm_g = (const float*)d_in[21];
    const float* vnorm_b = (const float*)d_in[22];
    const float* lin1_w  = (const float*)d_in[23];
    const float* lin1_b  = (const float*)d_in[24];
    const float* lin2_w  = (const float*)d_in[25];
    const float* lin2_b  = (const float*)d_in[26];
    float* out = (float*)d_out;

    cudaFuncSetAttribute(logits_gemm_kernel,  cudaFuncAttributeMaxDynamicSharedMemorySize, GEMM_SMEM);
    cudaFuncSetAttribute(gemm_kernel,         cudaFuncAttributeMaxDynamicSharedMemorySize, GEMM_SMEM);
    cudaFuncSetAttribute(flash_e_gemm_kernel, cudaFuncAttributeMaxDynamicSharedMemorySize, EGEMM_SMEM);
    cudaFuncSetAttribute(lin1_gemm_kernel,    cudaFuncAttributeMaxDynamicSharedMemorySize, E3GEMM_SMEM);
    cudaFuncSetAttribute(proj_gemm_kernel,    cudaFuncAttributeMaxDynamicSharedMemorySize, E3GEMM_SMEM);
    cudaFuncSetAttribute(conv2_gemm_kernel,   cudaFuncAttributeMaxDynamicSharedMemorySize, C2GEMM_SMEM);

    conv1_kernel<<<(NB*16*150*5 + 255)/256, 256>>>(x, conv1_w, conv1_b);
    im2col_coords_kernel<<<(EROWS*96 + 255)/256, 256>>>();
    prep_all_kernel<<<(PREP_TOT + 255)/256, 256>>>(alin_w, qlin_w, klin_w, lin1_w,
                                                   kp_w, qp_w, vp_w, conv2_w);
    conv2_gemm_kernel<<<EROWS/128, 256, C2GEMM_SMEM>>>(conv2_b);
    {
        dim3 g(EROWS/128, 12);                     // (298, 12)
        proj_gemm_kernel<<<g, 256, E3GEMM_SMEM>>>(kp_b, qp_b, vp_b);
    }
    {
        dim3 g(NB, 3);
        ln_stats_kernel<<<g, 512>>>();
    }
    {
        dim3 g(PER_B/1024, NB, 3);
        ln_apply_kernel<<<g, 256>>>(knorm_g, knorm_b, qnorm_g, qnorm_b, vnorm_g, vnorm_b);
    }
    {
        dim3 g(KPAD/128, MROWS/128);               // (5, 1192)
        logits_gemm_kernel<<<g, 128, GEMM_SMEM>>>(qlin_b, klin_b);
    }
    {
        dim3 g(KPAD/128, MROWS/128);               // (5, 1192)
        gemm_kernel<<<g, 128, GEMM_SMEM>>>(alin_b);
    }
    vtrans_kernel<<<NB*HEADS, 256>>>();
    {
        dim3 g(5, NB*HEADS);                       // (5, 256)
        flash_e_gemm_kernel<<<g, 256, EGEMM_SMEM>>>();
    }
    lin1_gemm_kernel<<<EROWS/128, 256, E3GEMM_SMEM>>>(lin1_b);
    ln2_kernel<<<NB, 256>>>();
    final_kernel<<<3, 256>>>(lin2_w, lin2_b, out);
}